// round 2
// baseline (speedup 1.0000x reference)
#include <cuda_runtime.h>
#include <cuda.h>

#define NN 50000
#define NE 800000
#define H  128

// Scratch (device globals; no allocation allowed)
__device__ float g_x[NN * H];
__device__ float g_h[NN * H];
__device__ float g_agg[NN * H];
__device__ float g_inv[NN];
__device__ int   g_cnt[NN];

// ---------------------------------------------------------------------------
// init: gather x0 = emb[node_id], zero agg, zero cnt
// ---------------------------------------------------------------------------
__global__ __launch_bounds__(256) void k_init(const float* __restrict__ emb,
                                              const int* __restrict__ nid) {
    int i = blockIdx.x * blockDim.x + threadIdx.x;
    if (i < NN * H) {
        int r = i >> 7, c = i & 127;
        int n = nid[r];
        g_x[i]   = emb[(size_t)n * H + c];
        g_agg[i] = 0.0f;
    }
    if (i < NN) g_cnt[i] = 0;
}

__global__ __launch_bounds__(256) void k_count(const int* __restrict__ dst) {
    int e = blockIdx.x * blockDim.x + threadIdx.x;
    if (e < NE) atomicAdd(&g_cnt[dst[e]], 1);
}

__global__ __launch_bounds__(256) void k_inv() {
    int i = blockIdx.x * blockDim.x + threadIdx.x;
    if (i < NN) g_inv[i] = 1.0f / (float)max(g_cnt[i], 1);
}

// ---------------------------------------------------------------------------
// scatter: one warp per edge; agg[dst] += x[src]  (vector red.v4.f32)
// ---------------------------------------------------------------------------
__global__ __launch_bounds__(256) void k_scatter(const float* __restrict__ x,
                                                 const int* __restrict__ ei) {
    int wid  = (blockIdx.x * blockDim.x + threadIdx.x) >> 5;
    int lane = threadIdx.x & 31;
    if (wid >= NE) return;
    int s = ei[wid];
    int d = ei[NE + wid];
    float4 v = __ldg((const float4*)(x + (size_t)s * H) + lane);
    float* a = g_agg + (size_t)d * H + lane * 4;
    asm volatile("red.global.add.v4.f32 [%0], {%1,%2,%3,%4};"
                 :: "l"(a), "f"(v.x), "f"(v.y), "f"(v.z), "f"(v.w) : "memory");
}

// ---------------------------------------------------------------------------
// node transform: out = (agg*inv) @ Wl^T + x @ Wr^T + bl   (+relu)
// block = 256 threads = 8 warps, 32 nodes/block; each warp: 4 nodes,
// each lane: 4 consecutive outputs. Weights in smem as [k][o].
// ---------------------------------------------------------------------------
#define NPB 32
#define SMEM_NODE ((2 * H * H + 2 * NPB * H) * (int)sizeof(float))

template <bool RELU, bool ZEROAGG>
__global__ __launch_bounds__(256) void k_node(const float* __restrict__ x,
                                              const float* __restrict__ Wl,
                                              const float* __restrict__ bl,
                                              const float* __restrict__ Wr,
                                              float* __restrict__ out) {
    extern __shared__ float sh[];
    float* Wl_s = sh;                 // [k][o]
    float* Wr_s = sh + H * H;
    float* a_s  = sh + 2 * H * H;     // [NPB][H]
    float* x_s  = a_s + NPB * H;

    int tid = threadIdx.x;
    for (int i = tid; i < H * H; i += blockDim.x) {
        int o = i >> 7, k = i & 127;
        Wl_s[k * H + o] = Wl[i];
        Wr_s[k * H + o] = Wr[i];
    }
    int base = blockIdx.x * NPB;
    for (int i = tid; i < NPB * H; i += blockDim.x) {
        int nl = i >> 7, k = i & 127;
        int n = base + nl;
        float av = 0.0f, xv = 0.0f;
        if (n < NN) {
            size_t idx = (size_t)n * H + k;
            av = g_agg[idx] * g_inv[n];
            xv = x[idx];
            if (ZEROAGG) g_agg[idx] = 0.0f;
        }
        a_s[i] = av;
        x_s[i] = xv;
    }
    __syncthreads();

    int w = tid >> 5, lane = tid & 31;
    int o = lane * 4;
    float4 bb = *(const float4*)(bl + o);
    float4 acc[4];
    acc[0] = bb; acc[1] = bb; acc[2] = bb; acc[3] = bb;

    const float4* Wl4 = (const float4*)Wl_s;
    const float4* Wr4 = (const float4*)Wr_s;
    const float* a0p = a_s + (w * 4 + 0) * H;
    const float* a1p = a_s + (w * 4 + 1) * H;
    const float* a2p = a_s + (w * 4 + 2) * H;
    const float* a3p = a_s + (w * 4 + 3) * H;
    const float* x0p = x_s + (w * 4 + 0) * H;
    const float* x1p = x_s + (w * 4 + 1) * H;
    const float* x2p = x_s + (w * 4 + 2) * H;
    const float* x3p = x_s + (w * 4 + 3) * H;

#pragma unroll 4
    for (int k = 0; k < H; k++) {
        float4 wl = Wl4[k * 32 + lane];
        float4 wr = Wr4[k * 32 + lane];
        float a0 = a0p[k], xx0 = x0p[k];
        float a1 = a1p[k], xx1 = x1p[k];
        float a2 = a2p[k], xx2 = x2p[k];
        float a3 = a3p[k], xx3 = x3p[k];
        acc[0].x += wl.x * a0 + wr.x * xx0;
        acc[0].y += wl.y * a0 + wr.y * xx0;
        acc[0].z += wl.z * a0 + wr.z * xx0;
        acc[0].w += wl.w * a0 + wr.w * xx0;
        acc[1].x += wl.x * a1 + wr.x * xx1;
        acc[1].y += wl.y * a1 + wr.y * xx1;
        acc[1].z += wl.z * a1 + wr.z * xx1;
        acc[1].w += wl.w * a1 + wr.w * xx1;
        acc[2].x += wl.x * a2 + wr.x * xx2;
        acc[2].y += wl.y * a2 + wr.y * xx2;
        acc[2].z += wl.z * a2 + wr.z * xx2;
        acc[2].w += wl.w * a2 + wr.w * xx2;
        acc[3].x += wl.x * a3 + wr.x * xx3;
        acc[3].y += wl.y * a3 + wr.y * xx3;
        acc[3].z += wl.z * a3 + wr.z * xx3;
        acc[3].w += wl.w * a3 + wr.w * xx3;
    }

#pragma unroll
    for (int j = 0; j < 4; j++) {
        int n = base + w * 4 + j;
        if (n < NN) {
            float4 v = acc[j];
            if (RELU) {
                v.x = fmaxf(v.x, 0.0f);
                v.y = fmaxf(v.y, 0.0f);
                v.z = fmaxf(v.z, 0.0f);
                v.w = fmaxf(v.w, 0.0f);
            }
            *(float4*)(out + (size_t)n * H + o) = v;
        }
    }
}

// ---------------------------------------------------------------------------
// edge output: out[e] = dot(x[src], x[dst]); one warp per edge
// ---------------------------------------------------------------------------
__global__ __launch_bounds__(256) void k_edge(const float* __restrict__ x,
                                              const int* __restrict__ ei,
                                              float* __restrict__ out) {
    int wid  = (blockIdx.x * blockDim.x + threadIdx.x) >> 5;
    int lane = threadIdx.x & 31;
    if (wid >= NE) return;
    int s = ei[wid];
    int d = ei[NE + wid];
    float4 a = __ldg((const float4*)(x + (size_t)s * H) + lane);
    float4 b = __ldg((const float4*)(x + (size_t)d * H) + lane);
    float v = a.x * b.x + a.y * b.y + a.z * b.z + a.w * b.w;
#pragma unroll
    for (int off = 16; off; off >>= 1) v += __shfl_xor_sync(0xFFFFFFFFu, v, off);
    if (lane == 0) out[wid] = v;
}

// ---------------------------------------------------------------------------
extern "C" void kernel_launch(void* const* d_in, const int* in_sizes, int n_in,
                              void* d_out, int out_size) {
    const int* nid = (const int*)d_in[0];
    const int* ei  = (const int*)d_in[1];
    const float* emb = (const float*)d_in[2];
    const float* Wl1 = (const float*)d_in[3];
    const float* bl1 = (const float*)d_in[4];
    const float* Wr1 = (const float*)d_in[5];
    const float* Wl2 = (const float*)d_in[6];
    const float* bl2 = (const float*)d_in[7];
    const float* Wr2 = (const float*)d_in[8];
    float* out = (float*)d_out;

    cudaFuncSetAttribute(k_node<true, true>,
                         cudaFuncAttributeMaxDynamicSharedMemorySize, SMEM_NODE);
    cudaFuncSetAttribute(k_node<false, false>,
                         cudaFuncAttributeMaxDynamicSharedMemorySize, SMEM_NODE);

    float *px, *ph;
    cudaGetSymbolAddress((void**)&px, g_x);
    cudaGetSymbolAddress((void**)&ph, g_h);

    int gridNH  = (NN * H + 255) / 256;
    int gridE   = (NE + 255) / 256;
    int gridN   = (NN + 255) / 256;
    int gridEW  = (NE * 32 + 255) / 256;   // warp-per-edge
    int gridNode = (NN + NPB - 1) / NPB;

    k_init<<<gridNH, 256>>>(emb, nid);
    k_count<<<gridE, 256>>>(ei + NE);
    k_inv<<<gridN, 256>>>();

    // Layer 1
    k_scatter<<<gridEW, 256>>>(px, ei);
    k_node<true, true><<<gridNode, 256, SMEM_NODE>>>(px, Wl1, bl1, Wr1, ph);

    // Layer 2
    k_scatter<<<gridEW, 256>>>(ph, ei);
    k_node<false, false><<<gridNode, 256, SMEM_NODE>>>(ph, Wl2, bl2, Wr2, px);

    // Edge classifier
    k_edge<<<gridEW, 256>>>(px, ei, out);
}

// round 3
// speedup vs baseline: 1.1431x; 1.1431x over previous
#include <cuda_runtime.h>
#include <cuda.h>

#define NN 50000
#define NE 800000
#define H  128

// Scratch (device globals; no allocation allowed)
__device__ float g_x[NN * H];
__device__ float g_h[NN * H];
__device__ float g_agg[NN * H];
__device__ float g_inv[NN];
__device__ int   g_cnt[NN];
__device__ int   g_off[NN + 1];
__device__ int   g_pos[NN];
__device__ int   g_esrc[NE];

// ---------------------------------------------------------------------------
// init: gather x0 = emb[node_id], zero cnt
// ---------------------------------------------------------------------------
__global__ __launch_bounds__(256) void k_init(const float* __restrict__ emb,
                                              const int* __restrict__ nid) {
    int i = blockIdx.x * blockDim.x + threadIdx.x;
    if (i < NN * H) {
        int r = i >> 7, c = i & 127;
        int n = nid[r];
        g_x[i] = emb[(size_t)n * H + c];
    }
    if (i < NN) g_cnt[i] = 0;
}

__global__ __launch_bounds__(256) void k_count(const int* __restrict__ dst) {
    int e = blockIdx.x * blockDim.x + threadIdx.x;
    if (e < NE) atomicAdd(&g_cnt[dst[e]], 1);
}

// ---------------------------------------------------------------------------
// single-block prefix scan over counts -> g_off / g_pos, and g_inv
// ---------------------------------------------------------------------------
__global__ __launch_bounds__(1024) void k_scan() {
    __shared__ int warp_sums[32];
    __shared__ int s_carry;
    int tid = threadIdx.x;
    int lane = tid & 31, w = tid >> 5;
    if (tid == 0) s_carry = 0;
    __syncthreads();
    for (int base = 0; base < NN; base += 1024) {
        int i = base + tid;
        int v = (i < NN) ? g_cnt[i] : 0;
        int xs = v;
#pragma unroll
        for (int off = 1; off < 32; off <<= 1) {
            int t = __shfl_up_sync(0xFFFFFFFFu, xs, off);
            if (lane >= off) xs += t;
        }
        if (lane == 31) warp_sums[w] = xs;
        __syncthreads();
        if (w == 0) {
            int s = warp_sums[lane];
#pragma unroll
            for (int off = 1; off < 32; off <<= 1) {
                int t = __shfl_up_sync(0xFFFFFFFFu, s, off);
                if (lane >= off) s += t;
            }
            warp_sums[lane] = s;
        }
        __syncthreads();
        int incl = xs + (w > 0 ? warp_sums[w - 1] : 0) + s_carry;
        int excl = incl - v;
        if (i < NN) {
            g_off[i] = excl;
            g_pos[i] = excl;
            g_inv[i] = 1.0f / (float)max(v, 1);
        }
        __syncthreads();
        if (tid == 1023) s_carry = incl;
        __syncthreads();
    }
    if (tid == 0) g_off[NN] = s_carry;
}

__global__ __launch_bounds__(256) void k_fill(const int* __restrict__ ei) {
    int e = blockIdx.x * blockDim.x + threadIdx.x;
    if (e >= NE) return;
    int s = ei[e];
    int d = ei[NE + e];
    int slot = atomicAdd(&g_pos[d], 1);
    g_esrc[slot] = s;
}

// ---------------------------------------------------------------------------
// aggregate (gather form): one warp per node; agg[n] = mean_{e: dst=n} x[src[e]]
// ---------------------------------------------------------------------------
__global__ __launch_bounds__(256) void k_aggr(const float* __restrict__ x) {
    int n = (blockIdx.x * blockDim.x + threadIdx.x) >> 5;
    int lane = threadIdx.x & 31;
    if (n >= NN) return;
    int beg = g_off[n], end = g_off[n + 1];
    float4 acc = make_float4(0.f, 0.f, 0.f, 0.f);
    int i = beg;
    for (; i + 4 <= end; i += 4) {
        int s0 = __ldg(&g_esrc[i + 0]);
        int s1 = __ldg(&g_esrc[i + 1]);
        int s2 = __ldg(&g_esrc[i + 2]);
        int s3 = __ldg(&g_esrc[i + 3]);
        float4 v0 = __ldg((const float4*)(x + (size_t)s0 * H) + lane);
        float4 v1 = __ldg((const float4*)(x + (size_t)s1 * H) + lane);
        float4 v2 = __ldg((const float4*)(x + (size_t)s2 * H) + lane);
        float4 v3 = __ldg((const float4*)(x + (size_t)s3 * H) + lane);
        acc.x += v0.x + v1.x + v2.x + v3.x;
        acc.y += v0.y + v1.y + v2.y + v3.y;
        acc.z += v0.z + v1.z + v2.z + v3.z;
        acc.w += v0.w + v1.w + v2.w + v3.w;
    }
    for (; i < end; i++) {
        int s = __ldg(&g_esrc[i]);
        float4 v = __ldg((const float4*)(x + (size_t)s * H) + lane);
        acc.x += v.x; acc.y += v.y; acc.z += v.z; acc.w += v.w;
    }
    float inv = g_inv[n];
    acc.x *= inv; acc.y *= inv; acc.z *= inv; acc.w *= inv;
    *(float4*)(g_agg + (size_t)n * H + lane * 4) = acc;
}

// ---------------------------------------------------------------------------
// node transform: out = agg @ Wl^T + x @ Wr^T + bl   (+relu)
// block = 256 threads = 8 warps, 32 nodes/block; each warp: 4 nodes,
// each lane: 4 consecutive outputs. Weights in smem as [k][o].
// ---------------------------------------------------------------------------
#define NPB 32
#define SMEM_NODE ((2 * H * H + 2 * NPB * H) * (int)sizeof(float))

template <bool RELU>
__global__ __launch_bounds__(256) void k_node(const float* __restrict__ x,
                                              const float* __restrict__ Wl,
                                              const float* __restrict__ bl,
                                              const float* __restrict__ Wr,
                                              float* __restrict__ out) {
    extern __shared__ float sh[];
    float* Wl_s = sh;                 // [k][o]
    float* Wr_s = sh + H * H;
    float* a_s  = sh + 2 * H * H;     // [NPB][H]
    float* x_s  = a_s + NPB * H;

    int tid = threadIdx.x;
    for (int i = tid; i < H * H; i += blockDim.x) {
        int o = i >> 7, k = i & 127;
        Wl_s[k * H + o] = Wl[i];
        Wr_s[k * H + o] = Wr[i];
    }
    int base = blockIdx.x * NPB;
    for (int i = tid; i < NPB * H; i += blockDim.x) {
        int nl = i >> 7, k = i & 127;
        int n = base + nl;
        float av = 0.0f, xv = 0.0f;
        if (n < NN) {
            size_t idx = (size_t)n * H + k;
            av = g_agg[idx];
            xv = x[idx];
        }
        a_s[i] = av;
        x_s[i] = xv;
    }
    __syncthreads();

    int w = tid >> 5, lane = tid & 31;
    int o = lane * 4;
    float4 bb = *(const float4*)(bl + o);
    float4 acc[4];
    acc[0] = bb; acc[1] = bb; acc[2] = bb; acc[3] = bb;

    const float4* Wl4 = (const float4*)Wl_s;
    const float4* Wr4 = (const float4*)Wr_s;
    const float* a0p = a_s + (w * 4 + 0) * H;
    const float* a1p = a_s + (w * 4 + 1) * H;
    const float* a2p = a_s + (w * 4 + 2) * H;
    const float* a3p = a_s + (w * 4 + 3) * H;
    const float* x0p = x_s + (w * 4 + 0) * H;
    const float* x1p = x_s + (w * 4 + 1) * H;
    const float* x2p = x_s + (w * 4 + 2) * H;
    const float* x3p = x_s + (w * 4 + 3) * H;

#pragma unroll 4
    for (int k = 0; k < H; k++) {
        float4 wl = Wl4[k * 32 + lane];
        float4 wr = Wr4[k * 32 + lane];
        float a0 = a0p[k], xx0 = x0p[k];
        float a1 = a1p[k], xx1 = x1p[k];
        float a2 = a2p[k], xx2 = x2p[k];
        float a3 = a3p[k], xx3 = x3p[k];
        acc[0].x += wl.x * a0 + wr.x * xx0;
        acc[0].y += wl.y * a0 + wr.y * xx0;
        acc[0].z += wl.z * a0 + wr.z * xx0;
        acc[0].w += wl.w * a0 + wr.w * xx0;
        acc[1].x += wl.x * a1 + wr.x * xx1;
        acc[1].y += wl.y * a1 + wr.y * xx1;
        acc[1].z += wl.z * a1 + wr.z * xx1;
        acc[1].w += wl.w * a1 + wr.w * xx1;
        acc[2].x += wl.x * a2 + wr.x * xx2;
        acc[2].y += wl.y * a2 + wr.y * xx2;
        acc[2].z += wl.z * a2 + wr.z * xx2;
        acc[2].w += wl.w * a2 + wr.w * xx2;
        acc[3].x += wl.x * a3 + wr.x * xx3;
        acc[3].y += wl.y * a3 + wr.y * xx3;
        acc[3].z += wl.z * a3 + wr.z * xx3;
        acc[3].w += wl.w * a3 + wr.w * xx3;
    }

#pragma unroll
    for (int j = 0; j < 4; j++) {
        int n = base + w * 4 + j;
        if (n < NN) {
            float4 v = acc[j];
            if (RELU) {
                v.x = fmaxf(v.x, 0.0f);
                v.y = fmaxf(v.y, 0.0f);
                v.z = fmaxf(v.z, 0.0f);
                v.w = fmaxf(v.w, 0.0f);
            }
            *(float4*)(out + (size_t)n * H + o) = v;
        }
    }
}

// ---------------------------------------------------------------------------
// edge output: out[e] = dot(x[src], x[dst]); one warp per edge
// ---------------------------------------------------------------------------
__global__ __launch_bounds__(256) void k_edge(const float* __restrict__ x,
                                              const int* __restrict__ ei,
                                              float* __restrict__ out) {
    int wid  = (blockIdx.x * blockDim.x + threadIdx.x) >> 5;
    int lane = threadIdx.x & 31;
    if (wid >= NE) return;
    int s = ei[wid];
    int d = ei[NE + wid];
    float4 a = __ldg((const float4*)(x + (size_t)s * H) + lane);
    float4 b = __ldg((const float4*)(x + (size_t)d * H) + lane);
    float v = a.x * b.x + a.y * b.y + a.z * b.z + a.w * b.w;
#pragma unroll
    for (int off = 16; off; off >>= 1) v += __shfl_xor_sync(0xFFFFFFFFu, v, off);
    if (lane == 0) out[wid] = v;
}

// ---------------------------------------------------------------------------
extern "C" void kernel_launch(void* const* d_in, const int* in_sizes, int n_in,
                              void* d_out, int out_size) {
    const int* nid = (const int*)d_in[0];
    const int* ei  = (const int*)d_in[1];
    const float* emb = (const float*)d_in[2];
    const float* Wl1 = (const float*)d_in[3];
    const float* bl1 = (const float*)d_in[4];
    const float* Wr1 = (const float*)d_in[5];
    const float* Wl2 = (const float*)d_in[6];
    const float* bl2 = (const float*)d_in[7];
    const float* Wr2 = (const float*)d_in[8];
    float* out = (float*)d_out;

    cudaFuncSetAttribute(k_node<true>,
                         cudaFuncAttributeMaxDynamicSharedMemorySize, SMEM_NODE);
    cudaFuncSetAttribute(k_node<false>,
                         cudaFuncAttributeMaxDynamicSharedMemorySize, SMEM_NODE);

    float *px, *ph;
    cudaGetSymbolAddress((void**)&px, g_x);
    cudaGetSymbolAddress((void**)&ph, g_h);

    int gridNH   = (NN * H + 255) / 256;
    int gridE    = (NE + 255) / 256;
    int gridNW   = (NN * 32 + 255) / 256;  // warp-per-node
    int gridEW   = (NE * 32 + 255) / 256;  // warp-per-edge
    int gridNode = (NN + NPB - 1) / NPB;

    // preprocessing: gather x0, build CSR (dst -> list of src)
    k_init<<<gridNH, 256>>>(emb, nid);
    k_count<<<gridE, 256>>>(ei + NE);
    k_scan<<<1, 1024>>>();
    k_fill<<<gridE, 256>>>(ei);

    // Layer 1
    k_aggr<<<gridNW, 256>>>(px);
    k_node<true><<<gridNode, 256, SMEM_NODE>>>(px, Wl1, bl1, Wr1, ph);

    // Layer 2
    k_aggr<<<gridNW, 256>>>(ph);
    k_node<false><<<gridNode, 256, SMEM_NODE>>>(ph, Wl2, bl2, Wr2, px);

    // Edge classifier
    k_edge<<<gridEW, 256>>>(px, ei, out);
}

// round 4
// speedup vs baseline: 1.2103x; 1.0588x over previous
#include <cuda_runtime.h>
#include <cuda.h>

#define NN 50000
#define NE 800000
#define H  128

// Scratch (device globals; no allocation allowed)
__device__ float g_x[NN * H];
__device__ float g_h[NN * H];
__device__ float g_agg[NN * H];
__device__ float g_inv[NN];
__device__ int   g_cnt[NN];
__device__ int   g_off[NN + 1];
__device__ int   g_pos[NN];
__device__ int2  g_epair[NE];   // {src, edge_id} bucketed by dst

// ---------------------------------------------------------------------------
// init: gather x0 = emb[node_id], zero cnt
// ---------------------------------------------------------------------------
__global__ __launch_bounds__(256) void k_init(const float* __restrict__ emb,
                                              const int* __restrict__ nid) {
    int i = blockIdx.x * blockDim.x + threadIdx.x;
    if (i < NN * H) {
        int r = i >> 7, c = i & 127;
        int n = nid[r];
        g_x[i] = emb[(size_t)n * H + c];
    }
    if (i < NN) g_cnt[i] = 0;
}

__global__ __launch_bounds__(256) void k_count(const int* __restrict__ dst) {
    int e = blockIdx.x * blockDim.x + threadIdx.x;
    if (e < NE) atomicAdd(&g_cnt[dst[e]], 1);
}

// ---------------------------------------------------------------------------
// single-block prefix scan over counts -> g_off / g_pos, and g_inv
// ---------------------------------------------------------------------------
__global__ __launch_bounds__(1024) void k_scan() {
    __shared__ int warp_sums[32];
    __shared__ int s_carry;
    int tid = threadIdx.x;
    int lane = tid & 31, w = tid >> 5;
    if (tid == 0) s_carry = 0;
    __syncthreads();
    for (int base = 0; base < NN; base += 1024) {
        int i = base + tid;
        int v = (i < NN) ? g_cnt[i] : 0;
        int xs = v;
#pragma unroll
        for (int off = 1; off < 32; off <<= 1) {
            int t = __shfl_up_sync(0xFFFFFFFFu, xs, off);
            if (lane >= off) xs += t;
        }
        if (lane == 31) warp_sums[w] = xs;
        __syncthreads();
        if (w == 0) {
            int s = warp_sums[lane];
#pragma unroll
            for (int off = 1; off < 32; off <<= 1) {
                int t = __shfl_up_sync(0xFFFFFFFFu, s, off);
                if (lane >= off) s += t;
            }
            warp_sums[lane] = s;
        }
        __syncthreads();
        int incl = xs + (w > 0 ? warp_sums[w - 1] : 0) + s_carry;
        int excl = incl - v;
        if (i < NN) {
            g_off[i] = excl;
            g_pos[i] = excl;
            g_inv[i] = 1.0f / (float)max(v, 1);
        }
        __syncthreads();
        if (tid == 1023) s_carry = incl;
        __syncthreads();
    }
    if (tid == 0) g_off[NN] = s_carry;
}

__global__ __launch_bounds__(256) void k_fill(const int* __restrict__ ei) {
    int e = blockIdx.x * blockDim.x + threadIdx.x;
    if (e >= NE) return;
    int s = ei[e];
    int d = ei[NE + e];
    int slot = atomicAdd(&g_pos[d], 1);
    g_epair[slot] = make_int2(s, e);
}

// ---------------------------------------------------------------------------
// aggregate (gather form): one warp per node; agg[n] = mean_{e: dst=n} x[src[e]]
// ---------------------------------------------------------------------------
__global__ __launch_bounds__(256) void k_aggr(const float* __restrict__ x) {
    int n = (blockIdx.x * blockDim.x + threadIdx.x) >> 5;
    int lane = threadIdx.x & 31;
    if (n >= NN) return;
    int beg = g_off[n], end = g_off[n + 1];
    float4 acc = make_float4(0.f, 0.f, 0.f, 0.f);
    int i = beg;
    for (; i + 4 <= end; i += 4) {
        int s0 = __ldg(&g_epair[i + 0].x);
        int s1 = __ldg(&g_epair[i + 1].x);
        int s2 = __ldg(&g_epair[i + 2].x);
        int s3 = __ldg(&g_epair[i + 3].x);
        float4 v0 = __ldg((const float4*)(x + (size_t)s0 * H) + lane);
        float4 v1 = __ldg((const float4*)(x + (size_t)s1 * H) + lane);
        float4 v2 = __ldg((const float4*)(x + (size_t)s2 * H) + lane);
        float4 v3 = __ldg((const float4*)(x + (size_t)s3 * H) + lane);
        acc.x += v0.x + v1.x + v2.x + v3.x;
        acc.y += v0.y + v1.y + v2.y + v3.y;
        acc.z += v0.z + v1.z + v2.z + v3.z;
        acc.w += v0.w + v1.w + v2.w + v3.w;
    }
    for (; i < end; i++) {
        int s = __ldg(&g_epair[i].x);
        float4 v = __ldg((const float4*)(x + (size_t)s * H) + lane);
        acc.x += v.x; acc.y += v.y; acc.z += v.z; acc.w += v.w;
    }
    float inv = g_inv[n];
    acc.x *= inv; acc.y *= inv; acc.z *= inv; acc.w *= inv;
    *(float4*)(g_agg + (size_t)n * H + lane * 4) = acc;
}

// ---------------------------------------------------------------------------
// node transform: out = agg @ Wl^T + x @ Wr^T + bl   (+relu)
// ---------------------------------------------------------------------------
#define NPB 32
#define SMEM_NODE ((2 * H * H + 2 * NPB * H) * (int)sizeof(float))

template <bool RELU>
__global__ __launch_bounds__(256) void k_node(const float* __restrict__ x,
                                              const float* __restrict__ Wl,
                                              const float* __restrict__ bl,
                                              const float* __restrict__ Wr,
                                              float* __restrict__ out) {
    extern __shared__ float sh[];
    float* Wl_s = sh;                 // [k][o]
    float* Wr_s = sh + H * H;
    float* a_s  = sh + 2 * H * H;     // [NPB][H]
    float* x_s  = a_s + NPB * H;

    int tid = threadIdx.x;
    for (int i = tid; i < H * H; i += blockDim.x) {
        int o = i >> 7, k = i & 127;
        Wl_s[k * H + o] = Wl[i];
        Wr_s[k * H + o] = Wr[i];
    }
    int base = blockIdx.x * NPB;
    for (int i = tid; i < NPB * H; i += blockDim.x) {
        int nl = i >> 7, k = i & 127;
        int n = base + nl;
        float av = 0.0f, xv = 0.0f;
        if (n < NN) {
            size_t idx = (size_t)n * H + k;
            av = g_agg[idx];
            xv = x[idx];
        }
        a_s[i] = av;
        x_s[i] = xv;
    }
    __syncthreads();

    int w = tid >> 5, lane = tid & 31;
    int o = lane * 4;
    float4 bb = *(const float4*)(bl + o);
    float4 acc[4];
    acc[0] = bb; acc[1] = bb; acc[2] = bb; acc[3] = bb;

    const float4* Wl4 = (const float4*)Wl_s;
    const float4* Wr4 = (const float4*)Wr_s;
    const float* a0p = a_s + (w * 4 + 0) * H;
    const float* a1p = a_s + (w * 4 + 1) * H;
    const float* a2p = a_s + (w * 4 + 2) * H;
    const float* a3p = a_s + (w * 4 + 3) * H;
    const float* x0p = x_s + (w * 4 + 0) * H;
    const float* x1p = x_s + (w * 4 + 1) * H;
    const float* x2p = x_s + (w * 4 + 2) * H;
    const float* x3p = x_s + (w * 4 + 3) * H;

#pragma unroll 4
    for (int k = 0; k < H; k++) {
        float4 wl = Wl4[k * 32 + lane];
        float4 wr = Wr4[k * 32 + lane];
        float a0 = a0p[k], xx0 = x0p[k];
        float a1 = a1p[k], xx1 = x1p[k];
        float a2 = a2p[k], xx2 = x2p[k];
        float a3 = a3p[k], xx3 = x3p[k];
        acc[0].x += wl.x * a0 + wr.x * xx0;
        acc[0].y += wl.y * a0 + wr.y * xx0;
        acc[0].z += wl.z * a0 + wr.z * xx0;
        acc[0].w += wl.w * a0 + wr.w * xx0;
        acc[1].x += wl.x * a1 + wr.x * xx1;
        acc[1].y += wl.y * a1 + wr.y * xx1;
        acc[1].z += wl.z * a1 + wr.z * xx1;
        acc[1].w += wl.w * a1 + wr.w * xx1;
        acc[2].x += wl.x * a2 + wr.x * xx2;
        acc[2].y += wl.y * a2 + wr.y * xx2;
        acc[2].z += wl.z * a2 + wr.z * xx2;
        acc[2].w += wl.w * a2 + wr.w * xx2;
        acc[3].x += wl.x * a3 + wr.x * xx3;
        acc[3].y += wl.y * a3 + wr.y * xx3;
        acc[3].z += wl.z * a3 + wr.z * xx3;
        acc[3].w += wl.w * a3 + wr.w * xx3;
    }

#pragma unroll
    for (int j = 0; j < 4; j++) {
        int n = base + w * 4 + j;
        if (n < NN) {
            float4 v = acc[j];
            if (RELU) {
                v.x = fmaxf(v.x, 0.0f);
                v.y = fmaxf(v.y, 0.0f);
                v.z = fmaxf(v.z, 0.0f);
                v.w = fmaxf(v.w, 0.0f);
            }
            *(float4*)(out + (size_t)n * H + o) = v;
        }
    }
}

// ---------------------------------------------------------------------------
// edge output via CSR: one warp per dst node; x[dst] cached in registers.
// out[eid] = dot(x[src], x[dst])
// ---------------------------------------------------------------------------
__device__ __forceinline__ float warp_red(float v) {
#pragma unroll
    for (int off = 16; off; off >>= 1) v += __shfl_xor_sync(0xFFFFFFFFu, v, off);
    return v;
}

__global__ __launch_bounds__(256) void k_edge_csr(const float* __restrict__ x,
                                                  float* __restrict__ out) {
    int n = (blockIdx.x * blockDim.x + threadIdx.x) >> 5;
    int lane = threadIdx.x & 31;
    if (n >= NN) return;
    int beg = g_off[n], end = g_off[n + 1];
    if (beg == end) return;
    float4 b = __ldg((const float4*)(x + (size_t)n * H) + lane);

    int i = beg;
    for (; i + 4 <= end; i += 4) {
        int2 p0 = __ldg(&g_epair[i + 0]);
        int2 p1 = __ldg(&g_epair[i + 1]);
        int2 p2 = __ldg(&g_epair[i + 2]);
        int2 p3 = __ldg(&g_epair[i + 3]);
        float4 a0 = __ldg((const float4*)(x + (size_t)p0.x * H) + lane);
        float4 a1 = __ldg((const float4*)(x + (size_t)p1.x * H) + lane);
        float4 a2 = __ldg((const float4*)(x + (size_t)p2.x * H) + lane);
        float4 a3 = __ldg((const float4*)(x + (size_t)p3.x * H) + lane);
        float v0 = a0.x * b.x + a0.y * b.y + a0.z * b.z + a0.w * b.w;
        float v1 = a1.x * b.x + a1.y * b.y + a1.z * b.z + a1.w * b.w;
        float v2 = a2.x * b.x + a2.y * b.y + a2.z * b.z + a2.w * b.w;
        float v3 = a3.x * b.x + a3.y * b.y + a3.z * b.z + a3.w * b.w;
        v0 = warp_red(v0);
        v1 = warp_red(v1);
        v2 = warp_red(v2);
        v3 = warp_red(v3);
        if (lane == 0) {
            out[p0.y] = v0;
            out[p1.y] = v1;
            out[p2.y] = v2;
            out[p3.y] = v3;
        }
    }
    for (; i < end; i++) {
        int2 p = __ldg(&g_epair[i]);
        float4 a = __ldg((const float4*)(x + (size_t)p.x * H) + lane);
        float v = a.x * b.x + a.y * b.y + a.z * b.z + a.w * b.w;
        v = warp_red(v);
        if (lane == 0) out[p.y] = v;
    }
}

// ---------------------------------------------------------------------------
extern "C" void kernel_launch(void* const* d_in, const int* in_sizes, int n_in,
                              void* d_out, int out_size) {
    const int* nid = (const int*)d_in[0];
    const int* ei  = (const int*)d_in[1];
    const float* emb = (const float*)d_in[2];
    const float* Wl1 = (const float*)d_in[3];
    const float* bl1 = (const float*)d_in[4];
    const float* Wr1 = (const float*)d_in[5];
    const float* Wl2 = (const float*)d_in[6];
    const float* bl2 = (const float*)d_in[7];
    const float* Wr2 = (const float*)d_in[8];
    float* out = (float*)d_out;

    cudaFuncSetAttribute(k_node<true>,
                         cudaFuncAttributeMaxDynamicSharedMemorySize, SMEM_NODE);
    cudaFuncSetAttribute(k_node<false>,
                         cudaFuncAttributeMaxDynamicSharedMemorySize, SMEM_NODE);

    float *px, *ph;
    cudaGetSymbolAddress((void**)&px, g_x);
    cudaGetSymbolAddress((void**)&ph, g_h);

    int gridNH   = (NN * H + 255) / 256;
    int gridE    = (NE + 255) / 256;
    int gridNW   = (NN * 32 + 255) / 256;  // warp-per-node
    int gridNode = (NN + NPB - 1) / NPB;

    // preprocessing: gather x0, build CSR (dst -> list of {src, eid})
    k_init<<<gridNH, 256>>>(emb, nid);
    k_count<<<gridE, 256>>>(ei + NE);
    k_scan<<<1, 1024>>>();
    k_fill<<<gridE, 256>>>(ei);

    // Layer 1
    k_aggr<<<gridNW, 256>>>(px);
    k_node<true><<<gridNode, 256, SMEM_NODE>>>(px, Wl1, bl1, Wr1, ph);

    // Layer 2
    k_aggr<<<gridNW, 256>>>(ph);
    k_node<false><<<gridNode, 256, SMEM_NODE>>>(ph, Wl2, bl2, Wr2, px);

    // Edge classifier (CSR form, dst-row register reuse)
    k_edge_csr<<<gridNW, 256>>>(px, out);
}

// round 5
// speedup vs baseline: 1.5241x; 1.2592x over previous
#include <cuda_runtime.h>
#include <cuda.h>
#include <cuda_fp16.h>

#define NN 50000
#define NE 800000
#define H  128

// Scratch (device globals; no allocation allowed)
__device__ float   g_x[NN * H];
__device__ float   g_h[NN * H];
__device__ float   g_agg[NN * H];
__device__ float   g_inv[NN];
__device__ int     g_cnt[NN];
__device__ int     g_off[NN + 1];
__device__ int     g_pos[NN];
__device__ int2    g_epair[NE];      // {src, edge_id} bucketed by dst
__device__ __half2 g_mx[NN * 64];    // fp16 mirror (x0, later final features)
__device__ __half2 g_mh[NN * 64];    // fp16 mirror of layer-1 output

// ---------------------------------------------------------------------------
// init: gather x0 = emb[node_id] (fp32 + fp16 mirror), zero cnt
// ---------------------------------------------------------------------------
__global__ __launch_bounds__(256) void k_init(const float* __restrict__ emb,
                                              const int* __restrict__ nid) {
    int i = blockIdx.x * blockDim.x + threadIdx.x;   // pair index
    if (i < NN * 64) {
        int r = i >> 6;
        int n = nid[r];
        float2 v = ((const float2*)(emb + (size_t)n * H))[i & 63];
        ((float2*)g_x)[i] = v;
        g_mx[i] = __floats2half2_rn(v.x, v.y);
    }
    if (i < NN) g_cnt[i] = 0;
}

__global__ __launch_bounds__(256) void k_count(const int* __restrict__ dst) {
    int e = blockIdx.x * blockDim.x + threadIdx.x;
    if (e < NE) atomicAdd(&g_cnt[dst[e]], 1);
}

// ---------------------------------------------------------------------------
// single-block prefix scan over counts -> g_off / g_pos, and g_inv
// ---------------------------------------------------------------------------
__global__ __launch_bounds__(1024) void k_scan() {
    __shared__ int warp_sums[32];
    __shared__ int s_carry;
    int tid = threadIdx.x;
    int lane = tid & 31, w = tid >> 5;
    if (tid == 0) s_carry = 0;
    __syncthreads();
    for (int base = 0; base < NN; base += 1024) {
        int i = base + tid;
        int v = (i < NN) ? g_cnt[i] : 0;
        int xs = v;
#pragma unroll
        for (int off = 1; off < 32; off <<= 1) {
            int t = __shfl_up_sync(0xFFFFFFFFu, xs, off);
            if (lane >= off) xs += t;
        }
        if (lane == 31) warp_sums[w] = xs;
        __syncthreads();
        if (w == 0) {
            int s = warp_sums[lane];
#pragma unroll
            for (int off = 1; off < 32; off <<= 1) {
                int t = __shfl_up_sync(0xFFFFFFFFu, s, off);
                if (lane >= off) s += t;
            }
            warp_sums[lane] = s;
        }
        __syncthreads();
        int incl = xs + (w > 0 ? warp_sums[w - 1] : 0) + s_carry;
        int excl = incl - v;
        if (i < NN) {
            g_off[i] = excl;
            g_pos[i] = excl;
            g_inv[i] = 1.0f / (float)max(v, 1);
        }
        __syncthreads();
        if (tid == 1023) s_carry = incl;
        __syncthreads();
    }
    if (tid == 0) g_off[NN] = s_carry;
}

__global__ __launch_bounds__(256) void k_fill(const int* __restrict__ ei) {
    int e = blockIdx.x * blockDim.x + threadIdx.x;
    if (e >= NE) return;
    int s = ei[e];
    int d = ei[NE + e];
    int slot = atomicAdd(&g_pos[d], 1);
    g_epair[slot] = make_int2(s, e);
}

// ---------------------------------------------------------------------------
// aggregate (gather, fp16 source): one warp per node
// ---------------------------------------------------------------------------
__device__ __forceinline__ float4 ld_row_h(const __half2* __restrict__ mx,
                                           int n, int lane) {
    uint2 raw = ((const uint2*)(mx + (size_t)n * 64))[lane];
    __half2 h0 = *reinterpret_cast<__half2*>(&raw.x);
    __half2 h1 = *reinterpret_cast<__half2*>(&raw.y);
    float2 f0 = __half22float2(h0);
    float2 f1 = __half22float2(h1);
    return make_float4(f0.x, f0.y, f1.x, f1.y);
}

__global__ __launch_bounds__(256) void k_aggr(const __half2* __restrict__ mx) {
    int n = (blockIdx.x * blockDim.x + threadIdx.x) >> 5;
    int lane = threadIdx.x & 31;
    if (n >= NN) return;
    int beg = g_off[n], end = g_off[n + 1];
    float4 acc = make_float4(0.f, 0.f, 0.f, 0.f);
    int i = beg;
    for (; i + 4 <= end; i += 4) {
        int s0 = __ldg(&g_epair[i + 0].x);
        int s1 = __ldg(&g_epair[i + 1].x);
        int s2 = __ldg(&g_epair[i + 2].x);
        int s3 = __ldg(&g_epair[i + 3].x);
        float4 v0 = ld_row_h(mx, s0, lane);
        float4 v1 = ld_row_h(mx, s1, lane);
        float4 v2 = ld_row_h(mx, s2, lane);
        float4 v3 = ld_row_h(mx, s3, lane);
        acc.x += v0.x + v1.x + v2.x + v3.x;
        acc.y += v0.y + v1.y + v2.y + v3.y;
        acc.z += v0.z + v1.z + v2.z + v3.z;
        acc.w += v0.w + v1.w + v2.w + v3.w;
    }
    for (; i < end; i++) {
        int s = __ldg(&g_epair[i].x);
        float4 v = ld_row_h(mx, s, lane);
        acc.x += v.x; acc.y += v.y; acc.z += v.z; acc.w += v.w;
    }
    float inv = g_inv[n];
    acc.x *= inv; acc.y *= inv; acc.z *= inv; acc.w *= inv;
    *(float4*)(g_agg + (size_t)n * H + lane * 4) = acc;
}

// ---------------------------------------------------------------------------
// node transform: out = agg @ Wl^T + x @ Wr^T + bl   (+relu)
// block = 256 threads = 8 warps, 64 nodes/block; each warp: 8 nodes,
// each lane: 4 consecutive outputs. Weights in smem as [k][o].
// Writes fp32 out (optional) + fp16 mirror.
// ---------------------------------------------------------------------------
#define NPB 64
#define SMEM_NODE ((2 * H * H + 2 * NPB * H) * (int)sizeof(float))

template <bool RELU, bool WRITEF32>
__global__ __launch_bounds__(256) void k_node(const float* __restrict__ x,
                                              const float* __restrict__ Wl,
                                              const float* __restrict__ bl,
                                              const float* __restrict__ Wr,
                                              float* __restrict__ out,
                                              __half2* __restrict__ mout) {
    extern __shared__ float sh[];
    float* Wl_s = sh;                 // [k][o]
    float* Wr_s = sh + H * H;
    float* a_s  = sh + 2 * H * H;     // [NPB][H]
    float* x_s  = a_s + NPB * H;

    int tid = threadIdx.x;
    for (int i = tid; i < H * H; i += blockDim.x) {
        int o = i >> 7, k = i & 127;
        Wl_s[k * H + o] = Wl[i];
        Wr_s[k * H + o] = Wr[i];
    }
    int base = blockIdx.x * NPB;
    for (int i = tid; i < NPB * H; i += blockDim.x) {
        int nl = i >> 7, k = i & 127;
        int n = base + nl;
        float av = 0.0f, xv = 0.0f;
        if (n < NN) {
            size_t idx = (size_t)n * H + k;
            av = g_agg[idx];
            xv = x[idx];
        }
        a_s[i] = av;
        x_s[i] = xv;
    }
    __syncthreads();

    int w = tid >> 5, lane = tid & 31;
    int o = lane * 4;
    float4 bb = *(const float4*)(bl + o);
    float4 acc[8];
#pragma unroll
    for (int j = 0; j < 8; j++) acc[j] = bb;

    const float4* Wl4 = (const float4*)Wl_s;
    const float4* Wr4 = (const float4*)Wr_s;
    const float* arow = a_s + (size_t)(w * 8) * H;
    const float* xrow = x_s + (size_t)(w * 8) * H;

#pragma unroll 2
    for (int k = 0; k < H; k++) {
        float4 wl = Wl4[k * 32 + lane];
        float4 wr = Wr4[k * 32 + lane];
#pragma unroll
        for (int j = 0; j < 8; j++) {
            float a  = arow[j * H + k];
            float xx = xrow[j * H + k];
            acc[j].x += wl.x * a + wr.x * xx;
            acc[j].y += wl.y * a + wr.y * xx;
            acc[j].z += wl.z * a + wr.z * xx;
            acc[j].w += wl.w * a + wr.w * xx;
        }
    }

#pragma unroll
    for (int j = 0; j < 8; j++) {
        int n = base + w * 8 + j;
        if (n < NN) {
            float4 v = acc[j];
            if (RELU) {
                v.x = fmaxf(v.x, 0.0f);
                v.y = fmaxf(v.y, 0.0f);
                v.z = fmaxf(v.z, 0.0f);
                v.w = fmaxf(v.w, 0.0f);
            }
            if (WRITEF32)
                *(float4*)(out + (size_t)n * H + o) = v;
            uint2 hv;
            __half2 h0 = __floats2half2_rn(v.x, v.y);
            __half2 h1 = __floats2half2_rn(v.z, v.w);
            hv.x = *reinterpret_cast<unsigned*>(&h0);
            hv.y = *reinterpret_cast<unsigned*>(&h1);
            ((uint2*)(mout + (size_t)n * 64))[lane] = hv;
        }
    }
}

// ---------------------------------------------------------------------------
// edge output via CSR (fp16 source): one warp per dst node; dst row in regs.
// ---------------------------------------------------------------------------
__device__ __forceinline__ float warp_red(float v) {
#pragma unroll
    for (int off = 16; off; off >>= 1) v += __shfl_xor_sync(0xFFFFFFFFu, v, off);
    return v;
}

__global__ __launch_bounds__(256) void k_edge_csr(const __half2* __restrict__ mx,
                                                  float* __restrict__ out) {
    int n = (blockIdx.x * blockDim.x + threadIdx.x) >> 5;
    int lane = threadIdx.x & 31;
    if (n >= NN) return;
    int beg = g_off[n], end = g_off[n + 1];
    if (beg == end) return;
    float4 b = ld_row_h(mx, n, lane);

    int i = beg;
    for (; i + 4 <= end; i += 4) {
        int2 p0 = __ldg(&g_epair[i + 0]);
        int2 p1 = __ldg(&g_epair[i + 1]);
        int2 p2 = __ldg(&g_epair[i + 2]);
        int2 p3 = __ldg(&g_epair[i + 3]);
        float4 a0 = ld_row_h(mx, p0.x, lane);
        float4 a1 = ld_row_h(mx, p1.x, lane);
        float4 a2 = ld_row_h(mx, p2.x, lane);
        float4 a3 = ld_row_h(mx, p3.x, lane);
        float v0 = a0.x * b.x + a0.y * b.y + a0.z * b.z + a0.w * b.w;
        float v1 = a1.x * b.x + a1.y * b.y + a1.z * b.z + a1.w * b.w;
        float v2 = a2.x * b.x + a2.y * b.y + a2.z * b.z + a2.w * b.w;
        float v3 = a3.x * b.x + a3.y * b.y + a3.z * b.z + a3.w * b.w;
        v0 = warp_red(v0);
        v1 = warp_red(v1);
        v2 = warp_red(v2);
        v3 = warp_red(v3);
        if (lane == 0) {
            out[p0.y] = v0;
            out[p1.y] = v1;
            out[p2.y] = v2;
            out[p3.y] = v3;
        }
    }
    for (; i < end; i++) {
        int2 p = __ldg(&g_epair[i]);
        float4 a = ld_row_h(mx, p.x, lane);
        float v = a.x * b.x + a.y * b.y + a.z * b.z + a.w * b.w;
        v = warp_red(v);
        if (lane == 0) out[p.y] = v;
    }
}

// ---------------------------------------------------------------------------
extern "C" void kernel_launch(void* const* d_in, const int* in_sizes, int n_in,
                              void* d_out, int out_size) {
    const int* nid = (const int*)d_in[0];
    const int* ei  = (const int*)d_in[1];
    const float* emb = (const float*)d_in[2];
    const float* Wl1 = (const float*)d_in[3];
    const float* bl1 = (const float*)d_in[4];
    const float* Wr1 = (const float*)d_in[5];
    const float* Wl2 = (const float*)d_in[6];
    const float* bl2 = (const float*)d_in[7];
    const float* Wr2 = (const float*)d_in[8];
    float* out = (float*)d_out;

    cudaFuncSetAttribute(k_node<true, true>,
                         cudaFuncAttributeMaxDynamicSharedMemorySize, SMEM_NODE);
    cudaFuncSetAttribute(k_node<false, false>,
                         cudaFuncAttributeMaxDynamicSharedMemorySize, SMEM_NODE);

    float *px, *ph;
    __half2 *pmx, *pmh;
    cudaGetSymbolAddress((void**)&px, g_x);
    cudaGetSymbolAddress((void**)&ph, g_h);
    cudaGetSymbolAddress((void**)&pmx, g_mx);
    cudaGetSymbolAddress((void**)&pmh, g_mh);

    int gridI    = (NN * 64 + 255) / 256;
    int gridE    = (NE + 255) / 256;
    int gridNW   = (NN * 32 + 255) / 256;  // warp-per-node
    int gridNode = (NN + NPB - 1) / NPB;

    // preprocessing: gather x0 (+mirror), build CSR (dst -> list of {src, eid})
    k_init<<<gridI, 256>>>(emb, nid);
    k_count<<<gridE, 256>>>(ei + NE);
    k_scan<<<1, 1024>>>();
    k_fill<<<gridE, 256>>>(ei);

    // Layer 1
    k_aggr<<<gridNW, 256>>>(pmx);
    k_node<true, true><<<gridNode, 256, SMEM_NODE>>>(px, Wl1, bl1, Wr1, ph, pmh);

    // Layer 2 (final features only needed as fp16 mirror for the edge dot)
    k_aggr<<<gridNW, 256>>>(pmh);
    k_node<false, false><<<gridNode, 256, SMEM_NODE>>>(ph, Wl2, bl2, Wr2, px, pmx);

    // Edge classifier (CSR form, dst-row register reuse)
    k_edge_csr<<<gridNW, 256>>>(pmx, out);
}

// round 6
// speedup vs baseline: 4.3702x; 2.8674x over previous
#include <cuda_runtime.h>
#include <cuda.h>
#include <cuda_fp16.h>

#define NN 50000
#define NE 800000
#define H  128

// Scratch (device globals; no allocation allowed)
__device__ float   g_inv[NN];
__device__ int     g_cnt[NN];
__device__ int     g_off[NN + 1];
__device__ int     g_pos[NN];
__device__ int2    g_epair[NE];                     // {src, edge_id} bucketed by dst
__device__ __align__(16) __half2 g_mx[NN * 64];     // x0 mirror; later final features
__device__ __align__(16) __half2 g_mh[NN * 64];     // layer-1 output
__device__ __align__(16) __half2 g_aggh[NN * 64];   // aggregation output (fp16)
__device__ __align__(16) __half  g_w1[H * 2 * H];   // [o][k] concat: k<128 = Wl, k>=128 = Wr
__device__ __align__(16) __half  g_w2[H * 2 * H];

// ---------------------------------------------------------------------------
// init: gather x0 = emb[node_id] -> fp16 mirror, zero cnt
// ---------------------------------------------------------------------------
__global__ __launch_bounds__(256) void k_init(const float* __restrict__ emb,
                                              const int* __restrict__ nid) {
    int i = blockIdx.x * blockDim.x + threadIdx.x;   // half2 index
    if (i < NN * 64) {
        int r = i >> 6;
        int n = nid[r];
        float2 v = ((const float2*)(emb + (size_t)n * H))[i & 63];
        g_mx[i] = __floats2half2_rn(v.x, v.y);
    }
    if (i < NN) g_cnt[i] = 0;
}

__global__ __launch_bounds__(256) void k_wconv(const float* __restrict__ Wl,
                                               const float* __restrict__ Wr,
                                               __half* __restrict__ wcat) {
    int i = blockIdx.x * blockDim.x + threadIdx.x;   // o*256 + k
    if (i < H * 2 * H) {
        int o = i >> 8, k = i & 255;
        float v = (k < H) ? Wl[o * H + k] : Wr[o * H + (k - H)];
        wcat[i] = __float2half(v);
    }
}

__global__ __launch_bounds__(256) void k_count(const int* __restrict__ dst) {
    int e = blockIdx.x * blockDim.x + threadIdx.x;
    if (e < NE) atomicAdd(&g_cnt[dst[e]], 1);
}

// ---------------------------------------------------------------------------
// single-block prefix scan over counts -> g_off / g_pos, and g_inv
// ---------------------------------------------------------------------------
__global__ __launch_bounds__(1024) void k_scan() {
    __shared__ int warp_sums[32];
    __shared__ int s_carry;
    int tid = threadIdx.x;
    int lane = tid & 31, w = tid >> 5;
    if (tid == 0) s_carry = 0;
    __syncthreads();
    for (int base = 0; base < NN; base += 1024) {
        int i = base + tid;
        int v = (i < NN) ? g_cnt[i] : 0;
        int xs = v;
#pragma unroll
        for (int off = 1; off < 32; off <<= 1) {
            int t = __shfl_up_sync(0xFFFFFFFFu, xs, off);
            if (lane >= off) xs += t;
        }
        if (lane == 31) warp_sums[w] = xs;
        __syncthreads();
        if (w == 0) {
            int s = warp_sums[lane];
#pragma unroll
            for (int off = 1; off < 32; off <<= 1) {
                int t = __shfl_up_sync(0xFFFFFFFFu, s, off);
                if (lane >= off) s += t;
            }
            warp_sums[lane] = s;
        }
        __syncthreads();
        int incl = xs + (w > 0 ? warp_sums[w - 1] : 0) + s_carry;
        int excl = incl - v;
        if (i < NN) {
            g_off[i] = excl;
            g_pos[i] = excl;
            g_inv[i] = 1.0f / (float)max(v, 1);
        }
        __syncthreads();
        if (tid == 1023) s_carry = incl;
        __syncthreads();
    }
    if (tid == 0) g_off[NN] = s_carry;
}

__global__ __launch_bounds__(256) void k_fill(const int* __restrict__ ei) {
    int e = blockIdx.x * blockDim.x + threadIdx.x;
    if (e >= NE) return;
    int s = ei[e];
    int d = ei[NE + e];
    int slot = atomicAdd(&g_pos[d], 1);
    g_epair[slot] = make_int2(s, e);
}

// ---------------------------------------------------------------------------
// aggregate (gather, fp16 in/out, fp32 accum): one warp per node
// ---------------------------------------------------------------------------
__device__ __forceinline__ float4 ld_row_h(const __half2* __restrict__ mx,
                                           int n, int lane) {
    uint2 raw = ((const uint2*)(mx + (size_t)n * 64))[lane];
    __half2 h0 = *reinterpret_cast<__half2*>(&raw.x);
    __half2 h1 = *reinterpret_cast<__half2*>(&raw.y);
    float2 f0 = __half22float2(h0);
    float2 f1 = __half22float2(h1);
    return make_float4(f0.x, f0.y, f1.x, f1.y);
}

__global__ __launch_bounds__(256) void k_aggr(const __half2* __restrict__ mx) {
    int n = (blockIdx.x * blockDim.x + threadIdx.x) >> 5;
    int lane = threadIdx.x & 31;
    if (n >= NN) return;
    int beg = g_off[n], end = g_off[n + 1];
    float4 acc = make_float4(0.f, 0.f, 0.f, 0.f);
    int i = beg;
    for (; i + 4 <= end; i += 4) {
        int s0 = __ldg(&g_epair[i + 0].x);
        int s1 = __ldg(&g_epair[i + 1].x);
        int s2 = __ldg(&g_epair[i + 2].x);
        int s3 = __ldg(&g_epair[i + 3].x);
        float4 v0 = ld_row_h(mx, s0, lane);
        float4 v1 = ld_row_h(mx, s1, lane);
        float4 v2 = ld_row_h(mx, s2, lane);
        float4 v3 = ld_row_h(mx, s3, lane);
        acc.x += v0.x + v1.x + v2.x + v3.x;
        acc.y += v0.y + v1.y + v2.y + v3.y;
        acc.z += v0.z + v1.z + v2.z + v3.z;
        acc.w += v0.w + v1.w + v2.w + v3.w;
    }
    for (; i < end; i++) {
        int s = __ldg(&g_epair[i].x);
        float4 v = ld_row_h(mx, s, lane);
        acc.x += v.x; acc.y += v.y; acc.z += v.z; acc.w += v.w;
    }
    float inv = g_inv[n];
    __half2 h0 = __floats2half2_rn(acc.x * inv, acc.y * inv);
    __half2 h1 = __floats2half2_rn(acc.z * inv, acc.w * inv);
    uint2 hv;
    hv.x = *reinterpret_cast<unsigned*>(&h0);
    hv.y = *reinterpret_cast<unsigned*>(&h1);
    ((uint2*)(g_aggh + (size_t)n * 64))[lane] = hv;
}

// ---------------------------------------------------------------------------
// node transform via tensor cores:
//   out[n][o] = sum_k A[n][k] * Wcat[o][k] + bl[o]   (+relu), A = [agg | x]
// block: 256 thr = 8 warps; tile m=128 n=128 k=256; warp = m32 x n64.
// A_s/W_s staged whole in smem (264-half pitch, conflict-free ldmatrix).
// ---------------------------------------------------------------------------
#define AK 264
#define SMEM_MMA (2 * 128 * AK * (int)sizeof(__half))

__device__ __forceinline__ void ldsm4(uint32_t addr, uint32_t& r0, uint32_t& r1,
                                      uint32_t& r2, uint32_t& r3) {
    asm volatile("ldmatrix.sync.aligned.m8n8.x4.shared.b16 {%0,%1,%2,%3}, [%4];"
                 : "=r"(r0), "=r"(r1), "=r"(r2), "=r"(r3) : "r"(addr));
}

__device__ __forceinline__ void mma16816(float* c, const uint32_t* a,
                                         uint32_t b0, uint32_t b1) {
    asm volatile(
        "mma.sync.aligned.m16n8k16.row.col.f32.f16.f16.f32 "
        "{%0,%1,%2,%3}, {%4,%5,%6,%7}, {%8,%9}, {%0,%1,%2,%3};"
        : "+f"(c[0]), "+f"(c[1]), "+f"(c[2]), "+f"(c[3])
        : "r"(a[0]), "r"(a[1]), "r"(a[2]), "r"(a[3]), "r"(b0), "r"(b1));
}

template <bool RELU>
__global__ __launch_bounds__(256) void k_node_mma(const __half2* __restrict__ aggh,
                                                  const __half2* __restrict__ xh,
                                                  const __half* __restrict__ wcat,
                                                  const float* __restrict__ bl,
                                                  __half2* __restrict__ mout) {
    extern __shared__ __half sh[];
    __half* A_s = sh;                 // [128][AK]
    __half* W_s = sh + 128 * AK;      // [128][AK]

    int tid = threadIdx.x;
    int base = blockIdx.x * 128;

    // stage A = [agg | x] rows (guarded), W rows
    for (int i = tid; i < 128 * 32; i += 256) {
        int row = i >> 5, q = i & 31;
        int n = base + row;
        uint4 v = make_uint4(0, 0, 0, 0);
        if (n < NN)
            v = (q < 16) ? ((const uint4*)aggh)[(size_t)n * 16 + q]
                         : ((const uint4*)xh)[(size_t)n * 16 + (q - 16)];
        *((uint4*)(A_s + (size_t)row * AK) + q) = v;
    }
    for (int i = tid; i < 128 * 32; i += 256) {
        int row = i >> 5, q = i & 31;
        *((uint4*)(W_s + (size_t)row * AK) + q) = ((const uint4*)wcat)[i];
    }
    __syncthreads();

    int wid = tid >> 5, lane = tid & 31;
    int wm = wid & 3, wn = wid >> 2;   // warp m (x4), warp n (x2)

    // ldmatrix per-lane addressing
    int lrow = (lane & 7) + (((lane >> 3) & 1) << 3);   // A: rows 0-7,8-15,0-7,8-15
    int lkh  = (lane >> 4) << 3;                        // A: k +0,+0,+8,+8
    uint32_t a_base[2];
#pragma unroll
    for (int mt = 0; mt < 2; mt++)
        a_base[mt] = (uint32_t)__cvta_generic_to_shared(
            A_s + (size_t)(wm * 32 + mt * 16 + lrow) * AK + lkh);

    int bnrow = (lane & 7) + (((lane >> 4) & 1) << 3);  // B: n rows g0,g0,g1,g1
    int bkh   = ((lane >> 3) & 1) << 3;                 // B: k +0,+8,+0,+8
    uint32_t b_base[4];
#pragma unroll
    for (int gp = 0; gp < 4; gp++)
        b_base[gp] = (uint32_t)__cvta_generic_to_shared(
            W_s + (size_t)(wn * 64 + gp * 16 + bnrow) * AK + bkh);

    float acc[2][8][4];
#pragma unroll
    for (int mt = 0; mt < 2; mt++)
#pragma unroll
        for (int g = 0; g < 8; g++)
#pragma unroll
            for (int j = 0; j < 4; j++) acc[mt][g][j] = 0.0f;

#pragma unroll 4
    for (int kc = 0; kc < 16; kc++) {
        uint32_t koff = kc * 32;   // 16 halves = 32 bytes
        uint32_t a[2][4];
        ldsm4(a_base[0] + koff, a[0][0], a[0][1], a[0][2], a[0][3]);
        ldsm4(a_base[1] + koff, a[1][0], a[1][1], a[1][2], a[1][3]);
#pragma unroll
        for (int gp = 0; gp < 4; gp++) {
            uint32_t b0, b1, b2, b3;
            ldsm4(b_base[gp] + koff, b0, b1, b2, b3);
#pragma unroll
            for (int mt = 0; mt < 2; mt++) {
                mma16816(acc[mt][gp * 2 + 0], a[mt], b0, b1);
                mma16816(acc[mt][gp * 2 + 1], a[mt], b2, b3);
            }
        }
    }

    // epilogue: bias + relu + fp16 store
    int r_in = lane >> 2;
    int cpair = (lane & 3) * 2;
#pragma unroll
    for (int mt = 0; mt < 2; mt++) {
#pragma unroll
        for (int g = 0; g < 8; g++) {
            int col = wn * 64 + g * 8 + cpair;
            float2 b2 = *(const float2*)(bl + col);
            float x0 = acc[mt][g][0] + b2.x;
            float y0 = acc[mt][g][1] + b2.y;
            float x1 = acc[mt][g][2] + b2.x;
            float y1 = acc[mt][g][3] + b2.y;
            if (RELU) {
                x0 = fmaxf(x0, 0.0f); y0 = fmaxf(y0, 0.0f);
                x1 = fmaxf(x1, 0.0f); y1 = fmaxf(y1, 0.0f);
            }
            int row0 = base + wm * 32 + mt * 16 + r_in;
            int row1 = row0 + 8;
            if (row0 < NN) mout[(size_t)row0 * 64 + (col >> 1)] = __floats2half2_rn(x0, y0);
            if (row1 < NN) mout[(size_t)row1 * 64 + (col >> 1)] = __floats2half2_rn(x1, y1);
        }
    }
}

// ---------------------------------------------------------------------------
// edge output via CSR (fp16 source): one warp per dst node; dst row in regs.
// ---------------------------------------------------------------------------
__device__ __forceinline__ float warp_red(float v) {
#pragma unroll
    for (int off = 16; off; off >>= 1) v += __shfl_xor_sync(0xFFFFFFFFu, v, off);
    return v;
}

__global__ __launch_bounds__(256) void k_edge_csr(const __half2* __restrict__ mx,
                                                  float* __restrict__ out) {
    int n = (blockIdx.x * blockDim.x + threadIdx.x) >> 5;
    int lane = threadIdx.x & 31;
    if (n >= NN) return;
    int beg = g_off[n], end = g_off[n + 1];
    if (beg == end) return;
    float4 b = ld_row_h(mx, n, lane);

    int i = beg;
    for (; i + 4 <= end; i += 4) {
        int2 p0 = __ldg(&g_epair[i + 0]);
        int2 p1 = __ldg(&g_epair[i + 1]);
        int2 p2 = __ldg(&g_epair[i + 2]);
        int2 p3 = __ldg(&g_epair[i + 3]);
        float4 a0 = ld_row_h(mx, p0.x, lane);
        float4 a1 = ld_row_h(mx, p1.x, lane);
        float4 a2 = ld_row_h(mx, p2.x, lane);
        float4 a3 = ld_row_h(mx, p3.x, lane);
        float v0 = a0.x * b.x + a0.y * b.y + a0.z * b.z + a0.w * b.w;
        float v1 = a1.x * b.x + a1.y * b.y + a1.z * b.z + a1.w * b.w;
        float v2 = a2.x * b.x + a2.y * b.y + a2.z * b.z + a2.w * b.w;
        float v3 = a3.x * b.x + a3.y * b.y + a3.z * b.z + a3.w * b.w;
        v0 = warp_red(v0);
        v1 = warp_red(v1);
        v2 = warp_red(v2);
        v3 = warp_red(v3);
        if (lane == 0) {
            out[p0.y] = v0;
            out[p1.y] = v1;
            out[p2.y] = v2;
            out[p3.y] = v3;
        }
    }
    for (; i < end; i++) {
        int2 p = __ldg(&g_epair[i]);
        float4 a = ld_row_h(mx, p.x, lane);
        float v = a.x * b.x + a.y * b.y + a.z * b.z + a.w * b.w;
        v = warp_red(v);
        if (lane == 0) out[p.y] = v;
    }
}

// ---------------------------------------------------------------------------
extern "C" void kernel_launch(void* const* d_in, const int* in_sizes, int n_in,
                              void* d_out, int out_size) {
    const int* nid = (const int*)d_in[0];
    const int* ei  = (const int*)d_in[1];
    const float* emb = (const float*)d_in[2];
    const float* Wl1 = (const float*)d_in[3];
    const float* bl1 = (const float*)d_in[4];
    const float* Wr1 = (const float*)d_in[5];
    const float* Wl2 = (const float*)d_in[6];
    const float* bl2 = (const float*)d_in[7];
    const float* Wr2 = (const float*)d_in[8];
    float* out = (float*)d_out;

    cudaFuncSetAttribute(k_node_mma<true>,
                         cudaFuncAttributeMaxDynamicSharedMemorySize, SMEM_MMA);
    cudaFuncSetAttribute(k_node_mma<false>,
                         cudaFuncAttributeMaxDynamicSharedMemorySize, SMEM_MMA);

    __half2 *pmx, *pmh, *pagg;
    __half *pw1, *pw2;
    cudaGetSymbolAddress((void**)&pmx, g_mx);
    cudaGetSymbolAddress((void**)&pmh, g_mh);
    cudaGetSymbolAddress((void**)&pagg, g_aggh);
    cudaGetSymbolAddress((void**)&pw1, g_w1);
    cudaGetSymbolAddress((void**)&pw2, g_w2);

    int gridI    = (NN * 64 + 255) / 256;
    int gridW    = (H * 2 * H + 255) / 256;
    int gridE    = (NE + 255) / 256;
    int gridNW   = (NN * 32 + 255) / 256;   // warp-per-node
    int gridMMA  = (NN + 127) / 128;

    // preprocessing
    k_init<<<gridI, 256>>>(emb, nid);
    k_wconv<<<gridW, 256>>>(Wl1, Wr1, pw1);
    k_wconv<<<gridW, 256>>>(Wl2, Wr2, pw2);
    k_count<<<gridE, 256>>>(ei + NE);
    k_scan<<<1, 1024>>>();
    k_fill<<<gridE, 256>>>(ei);

    // Layer 1
    k_aggr<<<gridNW, 256>>>(pmx);
    k_node_mma<true><<<gridMMA, 256, SMEM_MMA>>>(pagg, pmx, pw1, bl1, pmh);

    // Layer 2 (output overwrites g_mx)
    k_aggr<<<gridNW, 256>>>(pmh);
    k_node_mma<false><<<gridMMA, 256, SMEM_MMA>>>(pagg, pmh, pw2, bl2, pmx);

    // Edge classifier
    k_edge_csr<<<gridNW, 256>>>(pmx, out);
}

// round 7
// speedup vs baseline: 5.6127x; 1.2843x over previous
#include <cuda_runtime.h>
#include <cuda.h>
#include <cuda_fp16.h>

#define NN 50000
#define NE 800000
#define H  128
#define SCAN_B 1024
#define NBLK ((NN + SCAN_B - 1) / SCAN_B)   // 49

// Scratch (device globals; no allocation allowed)
__device__ float   g_inv[NN];
__device__ int     g_cnt[NN];
__device__ int     g_off[NN + 1];
__device__ int     g_pos[NN];
__device__ int     g_bsum[NBLK];
__device__ int2    g_epair[NE];                     // {src, edge_id} bucketed by dst
__device__ __align__(16) __half2 g_mx[NN * 64];     // x0 mirror; later final features
__device__ __align__(16) __half2 g_mh[NN * 64];     // layer-1 output
__device__ __align__(16) __half2 g_aggh[NN * 64];   // aggregation output (fp16)
__device__ __align__(16) __half  g_w1[H * 2 * H];   // [o][k] concat: k<128 = Wl, k>=128 = Wr
__device__ __align__(16) __half  g_w2[H * 2 * H];

// ---------------------------------------------------------------------------
// prep: gather x0 mirror, convert both weight mats, zero cnt
// ---------------------------------------------------------------------------
__global__ __launch_bounds__(256) void k_prep(const float* __restrict__ emb,
                                              const int* __restrict__ nid,
                                              const float* __restrict__ Wl1,
                                              const float* __restrict__ Wr1,
                                              const float* __restrict__ Wl2,
                                              const float* __restrict__ Wr2) {
    int i = blockIdx.x * blockDim.x + threadIdx.x;   // half2 index
    if (i < NN * 64) {
        int r = i >> 6;
        int n = nid[r];
        float2 v = ((const float2*)(emb + (size_t)n * H))[i & 63];
        g_mx[i] = __floats2half2_rn(v.x, v.y);
    }
    if (i < NN) g_cnt[i] = 0;
    if (i < H * 2 * H) {
        int o = i >> 8, k = i & 255;
        g_w1[i] = __float2half((k < H) ? Wl1[o * H + k] : Wr1[o * H + (k - H)]);
        g_w2[i] = __float2half((k < H) ? Wl2[o * H + k] : Wr2[o * H + (k - H)]);
    }
}

__global__ __launch_bounds__(256) void k_count(const int* __restrict__ dst) {
    int e = blockIdx.x * blockDim.x + threadIdx.x;
    if (e < NE) atomicAdd(&g_cnt[dst[e]], 1);
}

// ---------------------------------------------------------------------------
// parallel scan, phase A: block-local exclusive scan + block sums
// ---------------------------------------------------------------------------
__global__ __launch_bounds__(SCAN_B) void k_scanA() {
    __shared__ int warp_sums[32];
    int tid = threadIdx.x;
    int lane = tid & 31, w = tid >> 5;
    int i = blockIdx.x * SCAN_B + tid;
    int v = (i < NN) ? g_cnt[i] : 0;
    int xs = v;
#pragma unroll
    for (int off = 1; off < 32; off <<= 1) {
        int t = __shfl_up_sync(0xFFFFFFFFu, xs, off);
        if (lane >= off) xs += t;
    }
    if (lane == 31) warp_sums[w] = xs;
    __syncthreads();
    if (w == 0) {
        int s = warp_sums[lane];
#pragma unroll
        for (int off = 1; off < 32; off <<= 1) {
            int t = __shfl_up_sync(0xFFFFFFFFu, s, off);
            if (lane >= off) s += t;
        }
        warp_sums[lane] = s;
    }
    __syncthreads();
    int incl = xs + (w > 0 ? warp_sums[w - 1] : 0);
    if (i < NN) g_off[i] = incl - v;        // local exclusive
    if (tid == SCAN_B - 1) g_bsum[blockIdx.x] = incl;
}

// phase C: add preceding block sums; write off/pos/inv
__global__ __launch_bounds__(SCAN_B) void k_scanC() {
    __shared__ int s_base;
    int tid = threadIdx.x;
    int b = blockIdx.x;
    if (tid < 32) {
        int s = 0;
        for (int j = tid; j < b; j += 32) s += g_bsum[j];
#pragma unroll
        for (int off = 16; off; off >>= 1) s += __shfl_xor_sync(0xFFFFFFFFu, s, off);
        if (tid == 0) s_base = s;
    }
    __syncthreads();
    int i = b * SCAN_B + tid;
    if (i < NN) {
        int e = g_off[i] + s_base;
        g_off[i] = e;
        g_pos[i] = e;
        g_inv[i] = 1.0f / (float)max(g_cnt[i], 1);
    }
    if (i == 0) g_off[NN] = NE;
}

__global__ __launch_bounds__(256) void k_fill(const int* __restrict__ ei) {
    int e = blockIdx.x * blockDim.x + threadIdx.x;
    if (e >= NE) return;
    int s = ei[e];
    int d = ei[NE + e];
    int slot = atomicAdd(&g_pos[d], 1);
    g_epair[slot] = make_int2(s, e);
}

// ---------------------------------------------------------------------------
// aggregate (gather, fp16 in/out, fp32 accum): one warp per node
// ---------------------------------------------------------------------------
__device__ __forceinline__ float4 ld_row_h(const __half2* __restrict__ mx,
                                           int n, int lane) {
    uint2 raw = ((const uint2*)(mx + (size_t)n * 64))[lane];
    __half2 h0 = *reinterpret_cast<__half2*>(&raw.x);
    __half2 h1 = *reinterpret_cast<__half2*>(&raw.y);
    float2 f0 = __half22float2(h0);
    float2 f1 = __half22float2(h1);
    return make_float4(f0.x, f0.y, f1.x, f1.y);
}

__global__ __launch_bounds__(256) void k_aggr(const __half2* __restrict__ mx) {
    int n = (blockIdx.x * blockDim.x + threadIdx.x) >> 5;
    int lane = threadIdx.x & 31;
    if (n >= NN) return;
    int beg = g_off[n], end = g_off[n + 1];
    float4 acc = make_float4(0.f, 0.f, 0.f, 0.f);
    int i = beg;
    for (; i + 4 <= end; i += 4) {
        int s0 = __ldg(&g_epair[i + 0].x);
        int s1 = __ldg(&g_epair[i + 1].x);
        int s2 = __ldg(&g_epair[i + 2].x);
        int s3 = __ldg(&g_epair[i + 3].x);
        float4 v0 = ld_row_h(mx, s0, lane);
        float4 v1 = ld_row_h(mx, s1, lane);
        float4 v2 = ld_row_h(mx, s2, lane);
        float4 v3 = ld_row_h(mx, s3, lane);
        acc.x += v0.x + v1.x + v2.x + v3.x;
        acc.y += v0.y + v1.y + v2.y + v3.y;
        acc.z += v0.z + v1.z + v2.z + v3.z;
        acc.w += v0.w + v1.w + v2.w + v3.w;
    }
    for (; i < end; i++) {
        int s = __ldg(&g_epair[i].x);
        float4 v = ld_row_h(mx, s, lane);
        acc.x += v.x; acc.y += v.y; acc.z += v.z; acc.w += v.w;
    }
    float inv = g_inv[n];
    __half2 h0 = __floats2half2_rn(acc.x * inv, acc.y * inv);
    __half2 h1 = __floats2half2_rn(acc.z * inv, acc.w * inv);
    uint2 hv;
    hv.x = *reinterpret_cast<unsigned*>(&h0);
    hv.y = *reinterpret_cast<unsigned*>(&h1);
    ((uint2*)(g_aggh + (size_t)n * 64))[lane] = hv;
}

// ---------------------------------------------------------------------------
// node transform via tensor cores (m64 n128 k256 tile, 8 warps: 2m x 4n)
//   out[n][o] = sum_k A[n][k] * Wcat[o][k] + bl[o]   (+relu), A = [agg | x]
// ---------------------------------------------------------------------------
#define AK 264
#define MT 64
#define SMEM_MMA ((MT + 128) * AK * (int)sizeof(__half))

__device__ __forceinline__ void ldsm4(uint32_t addr, uint32_t& r0, uint32_t& r1,
                                      uint32_t& r2, uint32_t& r3) {
    asm volatile("ldmatrix.sync.aligned.m8n8.x4.shared.b16 {%0,%1,%2,%3}, [%4];"
                 : "=r"(r0), "=r"(r1), "=r"(r2), "=r"(r3) : "r"(addr));
}

__device__ __forceinline__ void mma16816(float* c, const uint32_t* a,
                                         uint32_t b0, uint32_t b1) {
    asm volatile(
        "mma.sync.aligned.m16n8k16.row.col.f32.f16.f16.f32 "
        "{%0,%1,%2,%3}, {%4,%5,%6,%7}, {%8,%9}, {%0,%1,%2,%3};"
        : "+f"(c[0]), "+f"(c[1]), "+f"(c[2]), "+f"(c[3])
        : "r"(a[0]), "r"(a[1]), "r"(a[2]), "r"(a[3]), "r"(b0), "r"(b1));
}

template <bool RELU>
__global__ __launch_bounds__(256) void k_node_mma(const __half2* __restrict__ aggh,
                                                  const __half2* __restrict__ xh,
                                                  const __half* __restrict__ wcat,
                                                  const float* __restrict__ bl,
                                                  __half2* __restrict__ mout) {
    extern __shared__ __half sh[];
    __half* A_s = sh;                 // [MT][AK]
    __half* W_s = sh + MT * AK;       // [128][AK]

    int tid = threadIdx.x;
    int base = blockIdx.x * MT;

    // stage A = [agg | x] rows (guarded), W rows
    for (int i = tid; i < MT * 32; i += 256) {
        int row = i >> 5, q = i & 31;
        int n = base + row;
        uint4 v = make_uint4(0, 0, 0, 0);
        if (n < NN)
            v = (q < 16) ? ((const uint4*)aggh)[(size_t)n * 16 + q]
                         : ((const uint4*)xh)[(size_t)n * 16 + (q - 16)];
        *((uint4*)(A_s + (size_t)row * AK) + q) = v;
    }
    for (int i = tid; i < 128 * 32; i += 256) {
        int row = i >> 5, q = i & 31;
        *((uint4*)(W_s + (size_t)row * AK) + q) = ((const uint4*)wcat)[i];
    }
    __syncthreads();

    int wid = tid >> 5, lane = tid & 31;
    int wm = wid & 1, wn = wid >> 1;   // warp m (x2), warp n (x4)

    // ldmatrix per-lane addressing
    int lrow = (lane & 7) + (((lane >> 3) & 1) << 3);   // A: rows 0-7,8-15,0-7,8-15
    int lkh  = (lane >> 4) << 3;                        // A: k +0,+0,+8,+8
    uint32_t a_base[2];
#pragma unroll
    for (int mt = 0; mt < 2; mt++)
        a_base[mt] = (uint32_t)__cvta_generic_to_shared(
            A_s + (size_t)(wm * 32 + mt * 16 + lrow) * AK + lkh);

    int bnrow = (lane & 7) + (((lane >> 4) & 1) << 3);  // B: n rows g0,g0,g1,g1
    int bkh   = ((lane >> 3) & 1) << 3;                 // B: k +0,+8,+0,+8
    uint32_t b_base[2];
#pragma unroll
    for (int gp = 0; gp < 2; gp++)
        b_base[gp] = (uint32_t)__cvta_generic_to_shared(
            W_s + (size_t)(wn * 32 + gp * 16 + bnrow) * AK + bkh);

    float acc[2][4][4];
#pragma unroll
    for (int mt = 0; mt < 2; mt++)
#pragma unroll
        for (int g = 0; g < 4; g++)
#pragma unroll
            for (int j = 0; j < 4; j++) acc[mt][g][j] = 0.0f;

#pragma unroll 4
    for (int kc = 0; kc < 16; kc++) {
        uint32_t koff = kc * 32;   // 16 halves = 32 bytes
        uint32_t a[2][4];
        ldsm4(a_base[0] + koff, a[0][0], a[0][1], a[0][2], a[0][3]);
        ldsm4(a_base[1] + koff, a[1][0], a[1][1], a[1][2], a[1][3]);
#pragma unroll
        for (int gp = 0; gp < 2; gp++) {
            uint32_t b0, b1, b2, b3;
            ldsm4(b_base[gp] + koff, b0, b1, b2, b3);
#pragma unroll
            for (int mt = 0; mt < 2; mt++) {
                mma16816(acc[mt][gp * 2 + 0], a[mt], b0, b1);
                mma16816(acc[mt][gp * 2 + 1], a[mt], b2, b3);
            }
        }
    }

    // epilogue: bias + relu + fp16 store
    int r_in = lane >> 2;
    int cpair = (lane & 3) * 2;
#pragma unroll
    for (int mt = 0; mt < 2; mt++) {
#pragma unroll
        for (int g = 0; g < 4; g++) {
            int col = wn * 32 + g * 8 + cpair;
            float2 b2 = *(const float2*)(bl + col);
            float x0 = acc[mt][g][0] + b2.x;
            float y0 = acc[mt][g][1] + b2.y;
            float x1 = acc[mt][g][2] + b2.x;
            float y1 = acc[mt][g][3] + b2.y;
            if (RELU) {
                x0 = fmaxf(x0, 0.0f); y0 = fmaxf(y0, 0.0f);
                x1 = fmaxf(x1, 0.0f); y1 = fmaxf(y1, 0.0f);
            }
            int row0 = base + wm * 32 + mt * 16 + r_in;
            int row1 = row0 + 8;
            if (row0 < NN) mout[(size_t)row0 * 64 + (col >> 1)] = __floats2half2_rn(x0, y0);
            if (row1 < NN) mout[(size_t)row1 * 64 + (col >> 1)] = __floats2half2_rn(x1, y1);
        }
    }
}

// ---------------------------------------------------------------------------
// edge output via CSR (fp16 source): one warp per dst node; dst row in regs.
// ---------------------------------------------------------------------------
__device__ __forceinline__ float warp_red(float v) {
#pragma unroll
    for (int off = 16; off; off >>= 1) v += __shfl_xor_sync(0xFFFFFFFFu, v, off);
    return v;
}

__global__ __launch_bounds__(256) void k_edge_csr(const __half2* __restrict__ mx,
                                                  float* __restrict__ out) {
    int n = (blockIdx.x * blockDim.x + threadIdx.x) >> 5;
    int lane = threadIdx.x & 31;
    if (n >= NN) return;
    int beg = g_off[n], end = g_off[n + 1];
    if (beg == end) return;
    float4 b = ld_row_h(mx, n, lane);

    int i = beg;
    for (; i + 4 <= end; i += 4) {
        int2 p0 = __ldg(&g_epair[i + 0]);
        int2 p1 = __ldg(&g_epair[i + 1]);
        int2 p2 = __ldg(&g_epair[i + 2]);
        int2 p3 = __ldg(&g_epair[i + 3]);
        float4 a0 = ld_row_h(mx, p0.x, lane);
        float4 a1 = ld_row_h(mx, p1.x, lane);
        float4 a2 = ld_row_h(mx, p2.x, lane);
        float4 a3 = ld_row_h(mx, p3.x, lane);
        float v0 = a0.x * b.x + a0.y * b.y + a0.z * b.z + a0.w * b.w;
        float v1 = a1.x * b.x + a1.y * b.y + a1.z * b.z + a1.w * b.w;
        float v2 = a2.x * b.x + a2.y * b.y + a2.z * b.z + a2.w * b.w;
        float v3 = a3.x * b.x + a3.y * b.y + a3.z * b.z + a3.w * b.w;
        v0 = warp_red(v0);
        v1 = warp_red(v1);
        v2 = warp_red(v2);
        v3 = warp_red(v3);
        if (lane == 0) {
            out[p0.y] = v0;
            out[p1.y] = v1;
            out[p2.y] = v2;
            out[p3.y] = v3;
        }
    }
    for (; i < end; i++) {
        int2 p = __ldg(&g_epair[i]);
        float4 a = ld_row_h(mx, p.x, lane);
        float v = a.x * b.x + a.y * b.y + a.z * b.z + a.w * b.w;
        v = warp_red(v);
        if (lane == 0) out[p.y] = v;
    }
}

// ---------------------------------------------------------------------------
extern "C" void kernel_launch(void* const* d_in, const int* in_sizes, int n_in,
                              void* d_out, int out_size) {
    const int* nid = (const int*)d_in[0];
    const int* ei  = (const int*)d_in[1];
    const float* emb = (const float*)d_in[2];
    const float* Wl1 = (const float*)d_in[3];
    const float* bl1 = (const float*)d_in[4];
    const float* Wr1 = (const float*)d_in[5];
    const float* Wl2 = (const float*)d_in[6];
    const float* bl2 = (const float*)d_in[7];
    const float* Wr2 = (const float*)d_in[8];
    float* out = (float*)d_out;

    cudaFuncSetAttribute(k_node_mma<true>,
                         cudaFuncAttributeMaxDynamicSharedMemorySize, SMEM_MMA);
    cudaFuncSetAttribute(k_node_mma<false>,
                         cudaFuncAttributeMaxDynamicSharedMemorySize, SMEM_MMA);

    __half2 *pmx, *pmh, *pagg;
    __half *pw1, *pw2;
    cudaGetSymbolAddress((void**)&pmx, g_mx);
    cudaGetSymbolAddress((void**)&pmh, g_mh);
    cudaGetSymbolAddress((void**)&pagg, g_aggh);
    cudaGetSymbolAddress((void**)&pw1, g_w1);
    cudaGetSymbolAddress((void**)&pw2, g_w2);

    int gridI    = (NN * 64 + 255) / 256;
    int gridE    = (NE + 255) / 256;
    int gridNW   = (NN * 32 + 255) / 256;   // warp-per-node
    int gridMMA  = (NN + MT - 1) / MT;

    // preprocessing
    k_prep<<<gridI, 256>>>(emb, nid, Wl1, Wr1, Wl2, Wr2);
    k_count<<<gridE, 256>>>(ei + NE);
    k_scanA<<<NBLK, SCAN_B>>>();
    k_scanC<<<NBLK, SCAN_B>>>();
    k_fill<<<gridE, 256>>>(ei);

    // Layer 1
    k_aggr<<<gridNW, 256>>>(pmx);
    k_node_mma<true><<<gridMMA, 256, SMEM_MMA>>>(pagg, pmx, pw1, bl1, pmh);

    // Layer 2 (output overwrites g_mx)
    k_aggr<<<gridNW, 256>>>(pmh);
    k_node_mma<false><<<gridMMA, 256, SMEM_MMA>>>(pagg, pmh, pw2, bl2, pmx);

    // Edge classifier
    k_edge_csr<<<gridNW, 256>>>(pmx, out);
}

// round 8
// speedup vs baseline: 5.7411x; 1.0229x over previous
#include <cuda_runtime.h>
#include <cuda.h>
#include <cuda_fp16.h>

#define NN 50000
#define NE 800000
#define H  128
#define SCAN_B 1024
#define NBLK ((NN + SCAN_B - 1) / SCAN_B)   // 49

// Scratch (device globals; no allocation allowed)
__device__ float   g_inv[NN];
__device__ int     g_cnt[NN];
__device__ int     g_off[NN + 1];
__device__ int     g_pos[NN];
__device__ int     g_bsum[NBLK];
__device__ int2    g_epair[NE];                     // {src, edge_id} bucketed by dst
__device__ __align__(16) __half2 g_mx[NN * 64];     // x0 mirror; later final features
__device__ __align__(16) __half2 g_mh[NN * 64];     // layer-1 output
__device__ __align__(16) __half2 g_aggh[NN * 64];   // aggregation output (fp16)
__device__ __align__(16) __half  g_w1[H * 2 * H];   // [o][k] concat: k<128 = Wl, k>=128 = Wr
__device__ __align__(16) __half  g_w2[H * 2 * H];

// ---------------------------------------------------------------------------
// prep: gather x0 mirror, convert both weight mats, zero cnt
// ---------------------------------------------------------------------------
__global__ __launch_bounds__(256) void k_prep(const float* __restrict__ emb,
                                              const int* __restrict__ nid,
                                              const float* __restrict__ Wl1,
                                              const float* __restrict__ Wr1,
                                              const float* __restrict__ Wl2,
                                              const float* __restrict__ Wr2) {
    int i = blockIdx.x * blockDim.x + threadIdx.x;   // half2 index
    if (i < NN * 64) {
        int r = i >> 6;
        int n = nid[r];
        float2 v = ((const float2*)(emb + (size_t)n * H))[i & 63];
        g_mx[i] = __floats2half2_rn(v.x, v.y);
    }
    if (i < NN) g_cnt[i] = 0;
    if (i < H * 2 * H) {
        int o = i >> 8, k = i & 255;
        g_w1[i] = __float2half((k < H) ? Wl1[o * H + k] : Wr1[o * H + (k - H)]);
        g_w2[i] = __float2half((k < H) ? Wl2[o * H + k] : Wr2[o * H + (k - H)]);
    }
}

__global__ __launch_bounds__(256) void k_count(const int* __restrict__ dst) {
    int e = blockIdx.x * blockDim.x + threadIdx.x;
    if (e < NE) atomicAdd(&g_cnt[dst[e]], 1);
}

// ---------------------------------------------------------------------------
// parallel scan, phase A: block-local exclusive scan + block sums
// ---------------------------------------------------------------------------
__global__ __launch_bounds__(SCAN_B) void k_scanA() {
    __shared__ int warp_sums[32];
    int tid = threadIdx.x;
    int lane = tid & 31, w = tid >> 5;
    int i = blockIdx.x * SCAN_B + tid;
    int v = (i < NN) ? g_cnt[i] : 0;
    int xs = v;
#pragma unroll
    for (int off = 1; off < 32; off <<= 1) {
        int t = __shfl_up_sync(0xFFFFFFFFu, xs, off);
        if (lane >= off) xs += t;
    }
    if (lane == 31) warp_sums[w] = xs;
    __syncthreads();
    if (w == 0) {
        int s = warp_sums[lane];
#pragma unroll
        for (int off = 1; off < 32; off <<= 1) {
            int t = __shfl_up_sync(0xFFFFFFFFu, s, off);
            if (lane >= off) s += t;
        }
        warp_sums[lane] = s;
    }
    __syncthreads();
    int incl = xs + (w > 0 ? warp_sums[w - 1] : 0);
    if (i < NN) g_off[i] = incl - v;        // local exclusive
    if (tid == SCAN_B - 1) g_bsum[blockIdx.x] = incl;
}

// phase C: add preceding block sums; write off/pos/inv
__global__ __launch_bounds__(SCAN_B) void k_scanC() {
    __shared__ int s_base;
    int tid = threadIdx.x;
    int b = blockIdx.x;
    if (tid < 32) {
        int s = 0;
        for (int j = tid; j < b; j += 32) s += g_bsum[j];
#pragma unroll
        for (int off = 16; off; off >>= 1) s += __shfl_xor_sync(0xFFFFFFFFu, s, off);
        if (tid == 0) s_base = s;
    }
    __syncthreads();
    int i = b * SCAN_B + tid;
    if (i < NN) {
        int e = g_off[i] + s_base;
        g_off[i] = e;
        g_pos[i] = e;
        g_inv[i] = 1.0f / (float)max(g_cnt[i], 1);
    }
    if (i == 0) g_off[NN] = NE;
}

__global__ __launch_bounds__(256) void k_fill(const int* __restrict__ ei) {
    int e = blockIdx.x * blockDim.x + threadIdx.x;
    if (e >= NE) return;
    int s = ei[e];
    int d = ei[NE + e];
    int slot = atomicAdd(&g_pos[d], 1);
    g_epair[slot] = make_int2(s, e);
}

// ---------------------------------------------------------------------------
// helpers: half-warp (16-lane) 128-bit row access
// ---------------------------------------------------------------------------
__device__ __forceinline__ void cvt8(const uint4& r, float* f) {
    __half2 h;
    float2 t;
    h = *reinterpret_cast<const __half2*>(&r.x); t = __half22float2(h); f[0] = t.x; f[1] = t.y;
    h = *reinterpret_cast<const __half2*>(&r.y); t = __half22float2(h); f[2] = t.x; f[3] = t.y;
    h = *reinterpret_cast<const __half2*>(&r.z); t = __half22float2(h); f[4] = t.x; f[5] = t.y;
    h = *reinterpret_cast<const __half2*>(&r.w); t = __half22float2(h); f[6] = t.x; f[7] = t.y;
}

__device__ __forceinline__ const uint4* rowq(const __half2* __restrict__ mx,
                                             int n, int q) {
    return (const uint4*)(mx + (size_t)n * 64) + q;
}

// ---------------------------------------------------------------------------
// aggregate: one warp per node, half-warp per edge row (LDG.128).
// group g = lane>>4 handles edges i+g, i+2+g, ... ; combine halves at end.
// ---------------------------------------------------------------------------
__global__ __launch_bounds__(256) void k_aggr(const __half2* __restrict__ mx) {
    int n = (blockIdx.x * blockDim.x + threadIdx.x) >> 5;
    int lane = threadIdx.x & 31;
    if (n >= NN) return;
    int g = lane >> 4, q = lane & 15;
    int beg = g_off[n], end = g_off[n + 1];
    float acc[8];
#pragma unroll
    for (int j = 0; j < 8; j++) acc[j] = 0.0f;

    int i = beg;
    for (; i + 8 <= end; i += 8) {
        int s0 = __ldg(&g_epair[i + 0 + g].x);
        int s1 = __ldg(&g_epair[i + 2 + g].x);
        int s2 = __ldg(&g_epair[i + 4 + g].x);
        int s3 = __ldg(&g_epair[i + 6 + g].x);
        uint4 r0 = __ldg(rowq(mx, s0, q));
        uint4 r1 = __ldg(rowq(mx, s1, q));
        uint4 r2 = __ldg(rowq(mx, s2, q));
        uint4 r3 = __ldg(rowq(mx, s3, q));
        float f0[8], f1[8], f2[8], f3[8];
        cvt8(r0, f0); cvt8(r1, f1); cvt8(r2, f2); cvt8(r3, f3);
#pragma unroll
        for (int j = 0; j < 8; j++) acc[j] += (f0[j] + f1[j]) + (f2[j] + f3[j]);
    }
    for (; i + 2 <= end; i += 2) {
        int s = __ldg(&g_epair[i + g].x);
        uint4 r = __ldg(rowq(mx, s, q));
        float f[8];
        cvt8(r, f);
#pragma unroll
        for (int j = 0; j < 8; j++) acc[j] += f[j];
    }
    if (i < end && g == 0) {   // odd tail: group 0 only
        int s = __ldg(&g_epair[i].x);
        uint4 r = __ldg(rowq(mx, s, q));
        float f[8];
        cvt8(r, f);
#pragma unroll
        for (int j = 0; j < 8; j++) acc[j] += f[j];
    }

    // combine the two halves (disjoint edge sets)
#pragma unroll
    for (int j = 0; j < 8; j++) acc[j] += __shfl_xor_sync(0xFFFFFFFFu, acc[j], 16);

    if (g == 0) {
        float inv = g_inv[n];
        uint4 hv;
        __half2 h;
        h = __floats2half2_rn(acc[0] * inv, acc[1] * inv); hv.x = *reinterpret_cast<unsigned*>(&h);
        h = __floats2half2_rn(acc[2] * inv, acc[3] * inv); hv.y = *reinterpret_cast<unsigned*>(&h);
        h = __floats2half2_rn(acc[4] * inv, acc[5] * inv); hv.z = *reinterpret_cast<unsigned*>(&h);
        h = __floats2half2_rn(acc[6] * inv, acc[7] * inv); hv.w = *reinterpret_cast<unsigned*>(&h);
        ((uint4*)(g_aggh + (size_t)n * 64))[q] = hv;
    }
}

// ---------------------------------------------------------------------------
// node transform via tensor cores (m64 n128 k256 tile, 8 warps: 2m x 4n)
//   out[n][o] = sum_k A[n][k] * Wcat[o][k] + bl[o]   (+relu), A = [agg | x]
// ---------------------------------------------------------------------------
#define AK 264
#define MT 64
#define SMEM_MMA ((MT + 128) * AK * (int)sizeof(__half))

__device__ __forceinline__ void ldsm4(uint32_t addr, uint32_t& r0, uint32_t& r1,
                                      uint32_t& r2, uint32_t& r3) {
    asm volatile("ldmatrix.sync.aligned.m8n8.x4.shared.b16 {%0,%1,%2,%3}, [%4];"
                 : "=r"(r0), "=r"(r1), "=r"(r2), "=r"(r3) : "r"(addr));
}

__device__ __forceinline__ void mma16816(float* c, const uint32_t* a,
                                         uint32_t b0, uint32_t b1) {
    asm volatile(
        "mma.sync.aligned.m16n8k16.row.col.f32.f16.f16.f32 "
        "{%0,%1,%2,%3}, {%4,%5,%6,%7}, {%8,%9}, {%0,%1,%2,%3};"
        : "+f"(c[0]), "+f"(c[1]), "+f"(c[2]), "+f"(c[3])
        : "r"(a[0]), "r"(a[1]), "r"(a[2]), "r"(a[3]), "r"(b0), "r"(b1));
}

template <bool RELU>
__global__ __launch_bounds__(256) void k_node_mma(const __half2* __restrict__ aggh,
                                                  const __half2* __restrict__ xh,
                                                  const __half* __restrict__ wcat,
                                                  const float* __restrict__ bl,
                                                  __half2* __restrict__ mout) {
    extern __shared__ __half sh[];
    __half* A_s = sh;                 // [MT][AK]
    __half* W_s = sh + MT * AK;       // [128][AK]

    int tid = threadIdx.x;
    int base = blockIdx.x * MT;

    // stage A = [agg | x] rows (guarded), W rows
    for (int i = tid; i < MT * 32; i += 256) {
        int row = i >> 5, q = i & 31;
        int n = base + row;
        uint4 v = make_uint4(0, 0, 0, 0);
        if (n < NN)
            v = (q < 16) ? ((const uint4*)aggh)[(size_t)n * 16 + q]
                         : ((const uint4*)xh)[(size_t)n * 16 + (q - 16)];
        *((uint4*)(A_s + (size_t)row * AK) + q) = v;
    }
    for (int i = tid; i < 128 * 32; i += 256) {
        int row = i >> 5, q = i & 31;
        *((uint4*)(W_s + (size_t)row * AK) + q) = ((const uint4*)wcat)[i];
    }
    __syncthreads();

    int wid = tid >> 5, lane = tid & 31;
    int wm = wid & 1, wn = wid >> 1;   // warp m (x2), warp n (x4)

    // ldmatrix per-lane addressing
    int lrow = (lane & 7) + (((lane >> 3) & 1) << 3);   // A: rows 0-7,8-15,0-7,8-15
    int lkh  = (lane >> 4) << 3;                        // A: k +0,+0,+8,+8
    uint32_t a_base[2];
#pragma unroll
    for (int mt = 0; mt < 2; mt++)
        a_base[mt] = (uint32_t)__cvta_generic_to_shared(
            A_s + (size_t)(wm * 32 + mt * 16 + lrow) * AK + lkh);

    int bnrow = (lane & 7) + (((lane >> 4) & 1) << 3);  // B: n rows g0,g0,g1,g1
    int bkh   = ((lane >> 3) & 1) << 3;                 // B: k +0,+8,+0,+8
    uint32_t b_base[2];
#pragma unroll
    for (int gp = 0; gp < 2; gp++)
        b_base[gp] = (uint32_t)__cvta_generic_to_shared(
            W_s + (size_t)(wn * 32 + gp * 16 + bnrow) * AK + bkh);

    float acc[2][4][4];
#pragma unroll
    for (int mt = 0; mt < 2; mt++)
#pragma unroll
        for (int g = 0; g < 4; g++)
#pragma unroll
            for (int j = 0; j < 4; j++) acc[mt][g][j] = 0.0f;

#pragma unroll 4
    for (int kc = 0; kc < 16; kc++) {
        uint32_t koff = kc * 32;   // 16 halves = 32 bytes
        uint32_t a[2][4];
        ldsm4(a_base[0] + koff, a[0][0], a[0][1], a[0][2], a[0][3]);
        ldsm4(a_base[1] + koff, a[1][0], a[1][1], a[1][2], a[1][3]);
#pragma unroll
        for (int gp = 0; gp < 2; gp++) {
            uint32_t b0, b1, b2, b3;
            ldsm4(b_base[gp] + koff, b0, b1, b2, b3);
#pragma unroll
            for (int mt = 0; mt < 2; mt++) {
                mma16816(acc[mt][gp * 2 + 0], a[mt], b0, b1);
                mma16816(acc[mt][gp * 2 + 1], a[mt], b2, b3);
            }
        }
    }

    // epilogue: bias + relu + fp16 store
    int r_in = lane >> 2;
    int cpair = (lane & 3) * 2;
#pragma unroll
    for (int mt = 0; mt < 2; mt++) {
#pragma unroll
        for (int g = 0; g < 4; g++) {
            int col = wn * 32 + g * 8 + cpair;
            float2 b2 = *(const float2*)(bl + col);
            float x0 = acc[mt][g][0] + b2.x;
            float y0 = acc[mt][g][1] + b2.y;
            float x1 = acc[mt][g][2] + b2.x;
            float y1 = acc[mt][g][3] + b2.y;
            if (RELU) {
                x0 = fmaxf(x0, 0.0f); y0 = fmaxf(y0, 0.0f);
                x1 = fmaxf(x1, 0.0f); y1 = fmaxf(y1, 0.0f);
            }
            int row0 = base + wm * 32 + mt * 16 + r_in;
            int row1 = row0 + 8;
            if (row0 < NN) mout[(size_t)row0 * 64 + (col >> 1)] = __floats2half2_rn(x0, y0);
            if (row1 < NN) mout[(size_t)row1 * 64 + (col >> 1)] = __floats2half2_rn(x1, y1);
        }
    }
}

// ---------------------------------------------------------------------------
// edge output via CSR: one warp per dst node, half-warp per edge (LDG.128).
// ---------------------------------------------------------------------------
__device__ __forceinline__ float half_red(float v) {
#pragma unroll
    for (int off = 8; off; off >>= 1) v += __shfl_xor_sync(0xFFFFFFFFu, v, off);
    return v;   // lanes 0 and 16 hold their group's sum
}

__device__ __forceinline__ float dot8(const float* a, const float* b) {
    return (a[0] * b[0] + a[1] * b[1]) + (a[2] * b[2] + a[3] * b[3])
         + (a[4] * b[4] + a[5] * b[5]) + (a[6] * b[6] + a[7] * b[7]);
}

__global__ __launch_bounds__(256) void k_edge_csr(const __half2* __restrict__ mx,
                                                  float* __restrict__ out) {
    int n = (blockIdx.x * blockDim.x + threadIdx.x) >> 5;
    int lane = threadIdx.x & 31;
    if (n >= NN) return;
    int q = lane & 15;
    int g = lane >> 4;
    int beg = g_off[n], end = g_off[n + 1];
    if (beg == end) return;

    float bf[8];
    {
        uint4 r = __ldg(rowq(mx, n, q));
        cvt8(r, bf);
    }

    int i = beg;
    for (; i + 8 <= end; i += 8) {
        int2 p0 = __ldg(&g_epair[i + 0 + g]);
        int2 p1 = __ldg(&g_epair[i + 2 + g]);
        int2 p2 = __ldg(&g_epair[i + 4 + g]);
        int2 p3 = __ldg(&g_epair[i + 6 + g]);
        uint4 r0 = __ldg(rowq(mx, p0.x, q));
        uint4 r1 = __ldg(rowq(mx, p1.x, q));
        uint4 r2 = __ldg(rowq(mx, p2.x, q));
        uint4 r3 = __ldg(rowq(mx, p3.x, q));
        float f[8];
        cvt8(r0, f); float v0 = half_red(dot8(f, bf));
        cvt8(r1, f); float v1 = half_red(dot8(f, bf));
        cvt8(r2, f); float v2 = half_red(dot8(f, bf));
        cvt8(r3, f); float v3 = half_red(dot8(f, bf));
        if (q == 0) {
            out[p0.y] = v0;
            out[p1.y] = v1;
            out[p2.y] = v2;
            out[p3.y] = v3;
        }
    }
    for (; i + 2 <= end; i += 2) {
        int2 p = __ldg(&g_epair[i + g]);
        uint4 r = __ldg(rowq(mx, p.x, q));
        float f[8];
        cvt8(r, f);
        float v = half_red(dot8(f, bf));
        if (q == 0) out[p.y] = v;
    }
    if (i < end) {   // odd tail: both groups compute the same edge; lane 0 writes
        int2 p = __ldg(&g_epair[i]);
        uint4 r = __ldg(rowq(mx, p.x, q));
        float f[8];
        cvt8(r, f);
        float v = half_red(dot8(f, bf));
        if (lane == 0) out[p.y] = v;
    }
}

// ---------------------------------------------------------------------------
extern "C" void kernel_launch(void* const* d_in, const int* in_sizes, int n_in,
                              void* d_out, int out_size) {
    const int* nid = (const int*)d_in[0];
    const int* ei  = (const int*)d_in[1];
    const float* emb = (const float*)d_in[2];
    const float* Wl1 = (const float*)d_in[3];
    const float* bl1 = (const float*)d_in[4];
    const float* Wr1 = (const float*)d_in[5];
    const float* Wl2 = (const float*)d_in[6];
    const float* bl2 = (const float*)d_in[7];
    const float* Wr2 = (const float*)d_in[8];
    float* out = (float*)d_out;

    cudaFuncSetAttribute(k_node_mma<true>,
                         cudaFuncAttributeMaxDynamicSharedMemorySize, SMEM_MMA);
    cudaFuncSetAttribute(k_node_mma<false>,
                         cudaFuncAttributeMaxDynamicSharedMemorySize, SMEM_MMA);

    __half2 *pmx, *pmh, *pagg;
    __half *pw1, *pw2;
    cudaGetSymbolAddress((void**)&pmx, g_mx);
    cudaGetSymbolAddress((void**)&pmh, g_mh);
    cudaGetSymbolAddress((void**)&pagg, g_aggh);
    cudaGetSymbolAddress((void**)&pw1, g_w1);
    cudaGetSymbolAddress((void**)&pw2, g_w2);

    int gridI    = (NN * 64 + 255) / 256;
    int gridE    = (NE + 255) / 256;
    int gridNW   = (NN * 32 + 255) / 256;   // warp-per-node
    int gridMMA  = (NN + MT - 1) / MT;

    // preprocessing
    k_prep<<<gridI, 256>>>(emb, nid, Wl1, Wr1, Wl2, Wr2);
    k_count<<<gridE, 256>>>(ei + NE);
    k_scanA<<<NBLK, SCAN_B>>>();
    k_scanC<<<NBLK, SCAN_B>>>();
    k_fill<<<gridE, 256>>>(ei);

    // Layer 1
    k_aggr<<<gridNW, 256>>>(pmx);
    k_node_mma<true><<<gridMMA, 256, SMEM_MMA>>>(pagg, pmx, pw1, bl1, pmh);

    // Layer 2 (output overwrites g_mx)
    k_aggr<<<gridNW, 256>>>(pmh);
    k_node_mma<false><<<gridMMA, 256, SMEM_MMA>>>(pagg, pmh, pw2, bl2, pmx);

    // Edge classifier
    k_edge_csr<<<gridNW, 256>>>(pmx, out);
}